// round 12
// baseline (speedup 1.0000x reference)
#include <cuda_runtime.h>
#include <math.h>

#define MTOT 16384   // B*S
#define G3   2304    // 3*H
#define HID  768
#define NC   9
#define GNB  96      // persistent GRU blocks (48 per dir)

// ---------------- device scratch ----------------
__device__ float g_qkv[(size_t)MTOT * G3];
__device__ float g_scores[(size_t)256 * 512 * 512];
__device__ float g_att[(size_t)MTOT * 768];
__device__ float g_x[(size_t)MTOT * 768];
__device__ float g_xwT[(size_t)2 * 512 * 32 * G3];     // [dir][s][b][G3]
__device__ float g_hseqT[(size_t)512 * 2 * 32 * 768];  // [s][dir][b][u]  (full precision, for FC)
__device__ float g_hseqR[(size_t)512 * 2 * 32 * 768];  // tf32-rounded copy (layer-1 GEMM input)
__device__ float g_hping[2 * 2 * 32 * HID];            // [parity][dir][b][u] (tf32-rounded)
__device__ int   g_flags[GNB];
__device__ float g_em[(size_t)MTOT * NC];
__device__ float g_nll[32];
__device__ float g_embr[(size_t)MTOT * 768];           // tf32-rounded emb
__device__ float g_wr[12976128];                       // tf32-rounded weights (see offsets)

// weight offsets in g_wr (floats)
#define WR_IPW   0                    // 2304*768
#define WR_OPW   1769472              // 768*768
#define WR_WIH0F 2359296              // 2304*768
#define WR_WIH0B 4128768              // 2304*768
#define WR_WIH1F 5898240              // 2304*1536
#define WR_WIH1B 9437184              // 2304*1536

// ---------------- tf32 helpers ----------------
__device__ __forceinline__ unsigned cvt_tf32(float v) {
    unsigned r;
    asm("cvt.rna.tf32.f32 %0, %1;" : "=r"(r) : "f"(v));
    return r;
}
__device__ __forceinline__ float round_tf32f(float v) {
    return __uint_as_float(cvt_tf32(v));
}
__device__ __forceinline__ void mma_tf32(float* c, const unsigned* a, const unsigned* b) {
    asm volatile(
        "mma.sync.aligned.m16n8k8.row.col.f32.tf32.tf32.f32 "
        "{%0,%1,%2,%3}, {%4,%5,%6,%7}, {%8,%9}, {%0,%1,%2,%3};"
        : "+f"(c[0]), "+f"(c[1]), "+f"(c[2]), "+f"(c[3])
        : "r"(a[0]), "r"(a[1]), "r"(a[2]), "r"(a[3]), "r"(b[0]), "r"(b[1]));
}

// ---------------- fast gate nonlinearities (1 MUFU each) ----------------
__device__ __forceinline__ float ftanh(float x) {
    float t;
    asm("tanh.approx.f32 %0, %1;" : "=f"(t) : "f"(x));
    return t;
}
__device__ __forceinline__ float fsig(float x) {
    float t;
    asm("tanh.approx.f32 %0, %1;" : "=f"(t) : "f"(x * 0.5f));
    return fmaf(0.5f, t, 0.5f);
}

// ---------------- cp.async helpers ----------------
__device__ __forceinline__ void cpa16(unsigned smem_addr, const void* gptr) {
    asm volatile("cp.async.cg.shared.global [%0], [%1], 16;" :: "r"(smem_addr), "l"(gptr));
}
__device__ __forceinline__ void cpa_commit() {
    asm volatile("cp.async.commit_group;");
}

// ---------------- elementwise RNA-round to tf32 ----------------
__global__ void __launch_bounds__(256) round_tf32_kernel(
    const float* __restrict__ src, float* __restrict__ dst, int n4)
{
    int i = blockIdx.x * 256 + threadIdx.x;
    int stride = gridDim.x * 256;
    for (; i < n4; i += stride) {
        float4 v = ((const float4*)src)[i];
        v.x = round_tf32f(v.x); v.y = round_tf32f(v.y);
        v.z = round_tf32f(v.z); v.w = round_tf32f(v.w);
        ((float4*)dst)[i] = v;
    }
}

// ---------------- tf32 tensor-core NT GEMM (cp.async pipeline; inputs pre-rounded) ----------------
// C[M,N] = A[M,K] @ B[N,K]^T + bias ; M%128==0, N%128==0, K%32==0
#define TG_BUF 4608               // 128*36 words per buffer
#define TG_SMEM (4 * TG_BUF * 4)  // A[2] + B[2] buffers, bytes

__global__ void __launch_bounds__(256) tgemm128(
    const float* __restrict__ A, const float* __restrict__ B,
    const float* __restrict__ bias, float* __restrict__ C,
    int M, int N, int K, int gatherA, int permC, int roundC)
{
    extern __shared__ unsigned smu[];
    unsigned* As = smu;               // [2][128][36]
    unsigned* Bs = smu + 2 * TG_BUF;  // [2][128][36]

    const int t = threadIdx.x;
    const int lane = t & 31;
    const int wid = t >> 5;
    const int wm = wid & 3;
    const int wn = wid >> 2;
    const int g  = lane >> 2;
    const int tg = lane & 3;

    const int row0 = blockIdx.y * 128;
    const int col0 = blockIdx.x * 128;

    const int grow = t >> 1;
    const int gk   = (t & 1) * 16;
    const int rowA = row0 + grow;

    size_t gb0 = 0, gb1 = 0;
    if (gatherA) {
        int bb = rowA >> 9, sq = rowA & 511;
        gb0 = ((size_t)(sq * 2) * 32 + bb) * 768;
        gb1 = ((size_t)(sq * 2 + 1) * 32 + bb) * 768;
    }
    const float* ArowP = A + (size_t)rowA * K;
    const float* BrowP = B + (size_t)(col0 + grow) * K;

    const unsigned sbA = (unsigned)__cvta_generic_to_shared(As) + (unsigned)((grow * 36 + gk) * 4);
    const unsigned sbB = (unsigned)__cvta_generic_to_shared(Bs) + (unsigned)((grow * 36 + gk) * 4);

    float acc[2][8][4];
#pragma unroll
    for (int mt = 0; mt < 2; mt++)
#pragma unroll
        for (int nt = 0; nt < 8; nt++)
#pragma unroll
            for (int q = 0; q < 4; q++) acc[mt][nt][q] = 0.f;

    const int nch = K >> 5;

    auto issue = [&](int kt, int buf) {
        const int o = (kt << 5) + gk;
        const float* ap;
        if (gatherA) ap = A + (o < 768 ? gb0 + o : gb1 + (o - 768));
        else         ap = ArowP + o;
        const float* bp = BrowP + o;
        const unsigned da = sbA + (unsigned)(buf * TG_BUF * 4);
        const unsigned db = sbB + (unsigned)(buf * TG_BUF * 4);
#pragma unroll
        for (int j = 0; j < 4; j++) {
            cpa16(da + j * 16, ap + j * 4);
            cpa16(db + j * 16, bp + j * 4);
        }
        cpa_commit();
    };

    issue(0, 0);
    int cur = 0;

    for (int kt = 0; kt < nch; kt++) {
        const bool more = (kt + 1) < nch;
        if (more) issue(kt + 1, cur ^ 1);
        if (more) asm volatile("cp.async.wait_group 1;");
        else      asm volatile("cp.async.wait_group 0;");
        __syncthreads();

        const unsigned* Ab = As + cur * TG_BUF;
        const unsigned* Bb = Bs + cur * TG_BUF;
#pragma unroll
        for (int ks = 0; ks < 4; ks++) {
            const int kk = ks * 8;
            unsigned af[2][4];
#pragma unroll
            for (int mt = 0; mt < 2; mt++) {
                const int r = wm * 32 + mt * 16 + g;
                af[mt][0] = Ab[(r)     * 36 + kk + tg];
                af[mt][1] = Ab[(r + 8) * 36 + kk + tg];
                af[mt][2] = Ab[(r)     * 36 + kk + tg + 4];
                af[mt][3] = Ab[(r + 8) * 36 + kk + tg + 4];
            }
            unsigned bf[8][2];
#pragma unroll
            for (int nt = 0; nt < 8; nt++) {
                const int n = wn * 64 + nt * 8 + g;
                bf[nt][0] = Bb[n * 36 + kk + tg];
                bf[nt][1] = Bb[n * 36 + kk + tg + 4];
            }
#pragma unroll
            for (int mt = 0; mt < 2; mt++)
#pragma unroll
                for (int nt = 0; nt < 8; nt++)
                    mma_tf32(acc[mt][nt], af[mt], bf[nt]);
        }
        __syncthreads();
        cur ^= 1;
    }

#pragma unroll
    for (int mt = 0; mt < 2; mt++) {
        const int r = row0 + wm * 32 + mt * 16 + g;
        int cr0 = r, cr1 = r + 8;
        if (permC) {
            cr0 = (r & 511) * 32 + (r >> 9);
            cr1 = ((r + 8) & 511) * 32 + ((r + 8) >> 9);
        }
#pragma unroll
        for (int nt = 0; nt < 8; nt++) {
            const int c = col0 + wn * 64 + nt * 8 + 2 * tg;
            const float b0 = bias[c], b1 = bias[c + 1];
            float2 v0 = make_float2(acc[mt][nt][0] + b0, acc[mt][nt][1] + b1);
            float2 v1 = make_float2(acc[mt][nt][2] + b0, acc[mt][nt][3] + b1);
            if (roundC) {
                v0.x = round_tf32f(v0.x); v0.y = round_tf32f(v0.y);
                v1.x = round_tf32f(v1.x); v1.y = round_tf32f(v1.y);
            }
            *(float2*)&C[(size_t)cr0 * N + c] = v0;
            *(float2*)&C[(size_t)cr1 * N + c] = v1;
        }
    }
}

// ---------------- attention scores = scale * Q K^T ----------------
__global__ void __launch_bounds__(256) attn_scores(void)
{
    __shared__ float Qs[16][64];
    __shared__ float Ks[16][64];
    const int bh = blockIdx.z, b = bh >> 3, h = bh & 7;
    const int row0 = blockIdx.y * 64, col0 = blockIdx.x * 64;
    const int t = threadIdx.x;
    const int lr = t & 63, lk = (t >> 6) << 2;
    const int tx = t & 15, ty = t >> 4;

    const float* Qp = g_qkv + ((size_t)b * 512 + row0 + lr) * G3 + h * 96 + lk;
    const float* Kp = g_qkv + ((size_t)b * 512 + col0 + lr) * G3 + 768 + h * 96 + lk;

    float acc[4][4];
#pragma unroll
    for (int i = 0; i < 4; i++)
#pragma unroll
        for (int j = 0; j < 4; j++) acc[i][j] = 0.f;

    for (int k0 = 0; k0 < 96; k0 += 16) {
        float4 qv = *(const float4*)(Qp + k0);
        float4 kv = *(const float4*)(Kp + k0);
        __syncthreads();
        Qs[lk + 0][lr] = qv.x; Qs[lk + 1][lr] = qv.y; Qs[lk + 2][lr] = qv.z; Qs[lk + 3][lr] = qv.w;
        Ks[lk + 0][lr] = kv.x; Ks[lk + 1][lr] = kv.y; Ks[lk + 2][lr] = kv.z; Ks[lk + 3][lr] = kv.w;
        __syncthreads();
#pragma unroll
        for (int kk = 0; kk < 16; kk++) {
            float a[4], c[4];
            *(float4*)a = *(const float4*)&Qs[kk][ty << 2];
            *(float4*)c = *(const float4*)&Ks[kk][tx << 2];
#pragma unroll
            for (int i = 0; i < 4; i++)
#pragma unroll
                for (int j = 0; j < 4; j++)
                    acc[i][j] = fmaf(a[i], c[j], acc[i][j]);
        }
    }
    const float scale = 0.1020620726159657f; // 1/sqrt(96)
    float* Cb = g_scores + (size_t)bh * 262144;
#pragma unroll
    for (int i = 0; i < 4; i++)
#pragma unroll
        for (int j = 0; j < 4; j++)
            Cb[(size_t)(row0 + (ty << 2) + i) * 512 + col0 + (tx << 2) + j] = acc[i][j] * scale;
}

// ---------------- softmax over rows of 512 (warp per row) ----------------
__global__ void __launch_bounds__(256) attn_softmax(void)
{
    const int warp = threadIdx.x >> 5, lane = threadIdx.x & 31;
    const size_t row = (size_t)blockIdx.x * 8 + warp;
    float* p = g_scores + row * 512;
    float v[16];
    float m = -1e30f;
#pragma unroll
    for (int i = 0; i < 16; i++) { v[i] = p[lane + (i << 5)]; m = fmaxf(m, v[i]); }
#pragma unroll
    for (int o = 16; o; o >>= 1) m = fmaxf(m, __shfl_xor_sync(0xffffffffu, m, o));
    float s = 0.f;
#pragma unroll
    for (int i = 0; i < 16; i++) { v[i] = expf(v[i] - m); s += v[i]; }
#pragma unroll
    for (int o = 16; o; o >>= 1) s += __shfl_xor_sync(0xffffffffu, s, o);
    const float inv = 1.f / s;
#pragma unroll
    for (int i = 0; i < 16; i++) p[lane + (i << 5)] = v[i] * inv;
}

// ---------------- O = P V  (stores att RNA-rounded) ----------------
__global__ void __launch_bounds__(256) attn_av(void)
{
    __shared__ float Ps[32][64];
    __shared__ float Vs[32][96];
    const int bh = blockIdx.y, b = bh >> 3, h = bh & 7;
    const int row0 = blockIdx.x * 64;
    const int t = threadIdx.x;
    const int tx = t & 15, ty = t >> 4;
    const int lr = t & 63, lk = (t >> 6) << 3;
    const int kr = t >> 3, cq = (t & 7) * 12;

    const float* Pp = g_scores + (size_t)bh * 262144 + (size_t)(row0 + lr) * 512 + lk;
    const float* Vp = g_qkv + ((size_t)b * 512 + kr) * G3 + 1536 + h * 96 + cq;

    float acc[4][6];
#pragma unroll
    for (int i = 0; i < 4; i++)
#pragma unroll
        for (int j = 0; j < 6; j++) acc[i][j] = 0.f;

    for (int k0 = 0; k0 < 512; k0 += 32) {
        float4 p0 = *(const float4*)(Pp + k0);
        float4 p1 = *(const float4*)(Pp + k0 + 4);
        const float* vp = Vp + (size_t)k0 * G3;
        float4 v0 = *(const float4*)(vp);
        float4 v1 = *(const float4*)(vp + 4);
        float4 v2 = *(const float4*)(vp + 8);
        __syncthreads();
        Ps[lk + 0][lr] = p0.x; Ps[lk + 1][lr] = p0.y; Ps[lk + 2][lr] = p0.z; Ps[lk + 3][lr] = p0.w;
        Ps[lk + 4][lr] = p1.x; Ps[lk + 5][lr] = p1.y; Ps[lk + 6][lr] = p1.z; Ps[lk + 7][lr] = p1.w;
        *(float4*)&Vs[kr][cq + 0] = v0;
        *(float4*)&Vs[kr][cq + 4] = v1;
        *(float4*)&Vs[kr][cq + 8] = v2;
        __syncthreads();
#pragma unroll
        for (int kk = 0; kk < 32; kk++) {
            float a[4];
            *(float4*)a = *(const float4*)&Ps[kk][ty << 2];
            const float* vr = &Vs[kk][tx * 6];
#pragma unroll
            for (int i = 0; i < 4; i++)
#pragma unroll
                for (int j = 0; j < 6; j++)
                    acc[i][j] = fmaf(a[i], vr[j], acc[i][j]);
        }
    }
#pragma unroll
    for (int i = 0; i < 4; i++) {
        size_t r = (size_t)b * 512 + row0 + (ty << 2) + i;
#pragma unroll
        for (int j = 0; j < 6; j++)
            g_att[r * 768 + h * 96 + tx * 6 + j] = round_tf32f(acc[i][j]);
    }
}

// ---------------- reset flags + h ping-pong ----------------
__global__ void gru_reset(void)
{
    int i = blockIdx.x * 256 + threadIdx.x;   // grid 384 x 256 = 98304
    if (i < GNB) g_flags[i] = 0;
    g_hping[i] = 0.f;
}

// ---------------- persistent tensor-core GRU layer ----------------
#define GRU_WSU  (48 * 768)              // W words
#define GRU_REDW (8 * 48 * 40)           // reduce buffer words (stride 40)
#define GRU_SMEM ((GRU_WSU + GRU_REDW) * 4)

__global__ void __launch_bounds__(256) gru_layer(
    const float* __restrict__ whhF, const float* __restrict__ whhB,
    const float* __restrict__ bhhF, const float* __restrict__ bhhB,
    int writeR)
{
    extern __shared__ unsigned smu[];
    unsigned* ws = smu;                       // [48][768] swizzled tf32
    float* red = (float*)(smu + GRU_WSU);     // [8][48*40]
    __shared__ float bsh[48];

    const int tid = threadIdx.x;
    const int warp = tid >> 5, lane = tid & 31;
    const int g = lane >> 2, tg = lane & 3;
    const int blk = blockIdx.x;
    const int dir = blk / 48, ub = blk % 48;
    const int u0 = ub * 16;
    const float* W   = dir ? whhB : whhF;
    const float* bhh = dir ? bhhB : bhhF;

    for (int r = warp; r < 48; r += 8) {
        const int gr = (r >> 4) * 768 + u0 + (r & 15);
        const unsigned sw = (unsigned)((r & 7) << 2);
        unsigned* dst = ws + r * 768;
        for (int k = lane; k < 768; k += 32)
            dst[k ^ sw] = cvt_tf32(W[(size_t)gr * 768 + k]);
    }
    if (tid < 48) bsh[tid] = bhh[(tid >> 4) * 768 + u0 + (tid & 15)];
    __syncthreads();

    const int kw0 = warp * 96;
    const int ul = tid & 15;
    const int b0 = tid >> 4;
    const int b1 = b0 + 16;

    for (int s = 0; s < 512; s++) {
        const int sx = dir ? (511 - s) : s;
        const float* xwrow = g_xwT + ((size_t)(dir * 512 + sx) * 32) * G3;

        const float* xp0 = xwrow + (size_t)b0 * G3 + u0 + ul;
        const float* xp1 = xwrow + (size_t)b1 * G3 + u0 + ul;
        const float xr0 = __ldcg(xp0), xz0 = __ldcg(xp0 + 768), xn0 = __ldcg(xp0 + 1536);
        const float xr1 = __ldcg(xp1), xz1 = __ldcg(xp1 + 768), xn1 = __ldcg(xp1 + 1536);

        if (s > 0) {
            if (tid < 48) {
                // PROVEN pattern (R8/R10): acquire on every poll, tight spin
                const int* fp = g_flags + dir * 48 + tid;
                int v;
                for (;;) {
                    asm volatile("ld.acquire.gpu.global.b32 %0, [%1];" : "=r"(v) : "l"(fp) : "memory");
                    if (v >= s) break;
                }
            }
            __syncthreads();
        }
        const float* hsrc = g_hping + (size_t)(((s & 1) * 2 + dir)) * 32 * 768;

        const float hold0 = __ldcg(&hsrc[(size_t)b0 * 768 + u0 + ul]);
        const float hold1 = __ldcg(&hsrc[(size_t)b1 * 768 + u0 + ul]);

        float acc[3][4][4];
#pragma unroll
        for (int mt = 0; mt < 3; mt++)
#pragma unroll
            for (int nt = 0; nt < 4; nt++)
#pragma unroll
                for (int q = 0; q < 4; q++) acc[mt][nt][q] = 0.f;

#pragma unroll
        for (int pass = 0; pass < 2; pass++) {
            unsigned bf[2][12][2];
#pragma unroll
            for (int np = 0; np < 2; np++) {
                const int bb = (pass * 2 + np) * 8 + g;
                const float* hb = hsrc + (size_t)bb * 768 + kw0;
#pragma unroll
                for (int kt = 0; kt < 12; kt++) {
                    bf[np][kt][0] = __float_as_uint(__ldcg(hb + kt * 8 + tg));
                    bf[np][kt][1] = __float_as_uint(__ldcg(hb + kt * 8 + tg + 4));
                }
            }
#pragma unroll
            for (int kt = 0; kt < 12; kt++) {
                const int kk = kw0 + kt * 8;
                unsigned af[3][4];
#pragma unroll
                for (int mt = 0; mt < 3; mt++) {
                    const int r = mt * 16 + g;
                    const unsigned sw = (unsigned)((r & 7) << 2);
                    const unsigned* wr  = ws + r * 768;
                    const unsigned* wr8 = ws + (r + 8) * 768;
                    af[mt][0] = wr [(kk + tg)     ^ sw];
                    af[mt][1] = wr8[(kk + tg)     ^ sw];
                    af[mt][2] = wr [(kk + tg + 4) ^ sw];
                    af[mt][3] = wr8[(kk + tg + 4) ^ sw];
                }
#pragma unroll
                for (int mt = 0; mt < 3; mt++) {
                    mma_tf32(acc[mt][pass * 2 + 0], af[mt], bf[0][kt]);
                    mma_tf32(acc[mt][pass * 2 + 1], af[mt], bf[1][kt]);
                }
            }
        }

        {
            float* rp = red + warp * (48 * 40);
#pragma unroll
            for (int mt = 0; mt < 3; mt++)
#pragma unroll
                for (int nt = 0; nt < 4; nt++) {
                    const int r = mt * 16 + g, c = nt * 8 + 2 * tg;
                    *(float2*)&rp[r * 40 + c]       = make_float2(acc[mt][nt][0], acc[mt][nt][1]);
                    *(float2*)&rp[(r + 8) * 40 + c] = make_float2(acc[mt][nt][2], acc[mt][nt][3]);
                }
        }
        __syncthreads();

        float* hdst = g_hping + (size_t)((((s & 1) ^ 1) * 2 + dir)) * 32 * 768;
        float* hq  = g_hseqT + ((size_t)(sx * 2 + dir) * 32) * 768;
        float* hqr = g_hseqR + ((size_t)(sx * 2 + dir) * 32) * 768;
        {
            float hr0 = bsh[ul], hz0 = bsh[16 + ul], hn0 = bsh[32 + ul];
            float hr1 = hr0, hz1 = hz0, hn1 = hn0;
#pragma unroll
            for (int w = 0; w < 8; w++) {
                const float* q = red + w * (48 * 40);
                hr0 += q[ul * 40 + b0];        hr1 += q[ul * 40 + b1];
                hz0 += q[(16 + ul) * 40 + b0]; hz1 += q[(16 + ul) * 40 + b1];
                hn0 += q[(32 + ul) * 40 + b0]; hn1 += q[(32 + ul) * 40 + b1];
            }
            const float rr0 = fsig(xr0 + hr0);
            const float zz0 = fsig(xz0 + hz0);
            const float nn0 = ftanh(fmaf(rr0, hn0, xn0));
            const float hnew0 = fmaf(zz0, hold0 - nn0, nn0);
            const float rr1 = fsig(xr1 + hr1);
            const float zz1 = fsig(xz1 + hz1);
            const float nn1 = ftanh(fmaf(rr1, hn1, xn1));
            const float hnew1 = fmaf(zz1, hold1 - nn1, nn1);
            const float r0q = round_tf32f(hnew0);
            const float r1q = round_tf32f(hnew1);
            hq[(size_t)b0 * 768 + u0 + ul] = hnew0;
            hq[(size_t)b1 * 768 + u0 + ul] = hnew1;
            if (writeR) {
                hqr[(size_t)b0 * 768 + u0 + ul] = r0q;
                hqr[(size_t)b1 * 768 + u0 + ul] = r1q;
            }
            hdst[(size_t)b0 * 768 + u0 + ul] = r0q;
            hdst[(size_t)b1 * 768 + u0 + ul] = r1q;
        }
        __syncthreads();
        if (tid == 0) {
            asm volatile("st.release.gpu.global.b32 [%0], %1;"
                         :: "l"(g_flags + blk), "r"(s + 1) : "memory");
        }
    }
}

// ---------------- FC: em = h1 @ fc_w^T + fc_b ----------------
__global__ void __launch_bounds__(256) fc_kernel(
    const float* __restrict__ fcw, const float* __restrict__ fcb)
{
    const int warp = threadIdx.x >> 5, lane = threadIdx.x & 31;
    const int row = blockIdx.x * 8 + warp;
    const int b = row >> 9, sq = row & 511;
    const float* h0p = g_hseqT + ((size_t)(sq * 2 + 0) * 32 + b) * 768;
    const float* h1p = g_hseqT + ((size_t)(sq * 2 + 1) * 32 + b) * 768;
    float s[NC];
#pragma unroll
    for (int c = 0; c < NC; c++) s[c] = 0.f;
    for (int k = lane; k < 768; k += 32) {
        const float hv0 = h0p[k];
        const float hv1 = h1p[k];
#pragma unroll
        for (int c = 0; c < NC; c++) {
            s[c] = fmaf(hv0, __ldg(&fcw[c * 1536 + k]), s[c]);
            s[c] = fmaf(hv1, __ldg(&fcw[c * 1536 + 768 + k]), s[c]);
        }
    }
#pragma unroll
    for (int c = 0; c < NC; c++) {
        float v = s[c];
#pragma unroll
        for (int o = 16; o; o >>= 1) v += __shfl_xor_sync(0xffffffffu, v, o);
        if (lane == 0) g_em[(size_t)row * NC + c] = v + fcb[c];
    }
}

// ---------------- CRF NLL (one warp per batch) ----------------
__global__ void crf_nll_kernel(
    const int* __restrict__ labels, const float* __restrict__ start,
    const float* __restrict__ endw, const float* __restrict__ trans)
{
    int b = blockIdx.x;
    int j = threadIdx.x;
    __shared__ float al[2][NC];
    __shared__ float tr[NC * NC];
    for (int i = j; i < NC * NC; i += 32) tr[i] = trans[i];
    const float* e = g_em + (size_t)b * 512 * NC;
    if (j < NC) al[0][j] = start[j] + e[j];
    __syncwarp();
    for (int t = 1; t < 512; t++) {
        int cur = t & 1, prv = cur ^ 1;
        if (j < NC) {
            float m = -1e30f;
#pragma unroll
            for (int i = 0; i < NC; i++) m = fmaxf(m, al[prv][i] + tr[i * NC + j]);
            float s = 0.f;
#pragma unroll
            for (int i = 0; i < NC; i++) s += expf(al[prv][i] + tr[i * NC + j] - m);
            al[cur][j] = m + logf(s) + e[t * NC + j];
        }
        __syncwarp();
    }
    const int* lab = labels + b * 512;
    float acc = 0.f;
    for (int t = j; t < 512; t += 32) acc += e[t * NC + lab[t]];
    for (int t = j; t < 511; t += 32) acc += tr[lab[t] * NC + lab[t + 1]];
#pragma unroll
    for (int o = 16; o; o >>= 1) acc += __shfl_xor_sync(0xffffffffu, acc, o);
    if (j == 0) {
        float m = -1e30f;
#pragma unroll
        for (int jj = 0; jj < NC; jj++) m = fmaxf(m, al[1][jj] + endw[jj]);
        float s = 0.f;
#pragma unroll
        for (int jj = 0; jj < NC; jj++) s += expf(al[1][jj] + endw[jj] - m);
        float denom = m + logf(s);
        float num = acc + start[lab[0]] + endw[lab[511]];
        g_nll[b] = denom - num;
    }
}

__global__ void finalize_loss(float* out)
{
    float s = 0.f;
    for (int i = 0; i < 32; i++) s += g_nll[i];
    out[0] = s;
}

// ---------------- Viterbi (one warp per batch) ----------------
__global__ void viterbi_kernel(
    const float* __restrict__ start, const float* __restrict__ endw,
    const float* __restrict__ trans, float* __restrict__ out)
{
    int b = blockIdx.x;
    int j = threadIdx.x;
    __shared__ float al[2][NC];
    __shared__ float tr[NC * NC];
    __shared__ unsigned char bp[511][NC];
    for (int i = j; i < NC * NC; i += 32) tr[i] = trans[i];
    const float* e = g_em + (size_t)b * 512 * NC;
    if (j < NC) al[0][j] = start[j] + e[j];
    __syncwarp();
    for (int t = 1; t < 512; t++) {
        int cur = t & 1, prv = cur ^ 1;
        if (j < NC) {
            float best = -1e30f;
            int arg = 0;
#pragma unroll
            for (int i = 0; i < NC; i++) {
                float sc = al[prv][i] + tr[i * NC + j];
                if (sc > best) { best = sc; arg = i; }
            }
            al[cur][j] = best + e[t * NC + j];
            bp[t - 1][j] = (unsigned char)arg;
        }
        __syncwarp();
    }
    if (j == 0) {
        float best = -1e30f;
        int last = 0;
#pragma unroll
        for (int jj = 0; jj < NC; jj++) {
            float sc = al[1][jj] + endw[jj];
            if (sc > best) { best = sc; last = jj; }
        }
        float* po = out + 1 + (size_t)b * 512;
        po[511] = (float)last;
        int tag = last;
        for (int t = 510; t >= 0; t--) {
            tag = bp[t][tag];
            po[t] = (float)tag;
        }
    }
}

// ---------------- launch ----------------
extern "C" void kernel_launch(void* const* d_in, const int* in_sizes, int n_in,
                              void* d_out, int out_size)
{
    const float* emb   = (const float*)d_in[0];
    const float* ipw   = (const float*)d_in[1];
    const float* ipb   = (const float*)d_in[2];
    const float* opw   = (const float*)d_in[3];
    const float* opb   = (const float*)d_in[4];
    const float* fcw   = (const float*)d_in[5];
    const float* fcb   = (const float*)d_in[6];
    const float* cstart= (const float*)d_in[7];
    const float* cend  = (const float*)d_in[8];
    const float* ctr   = (const float*)d_in[9];
    const int*   lab   = (const int*)d_in[10];
    const float* wih0f = (const float*)d_in[11];
    const float* whh0f = (const float*)d_in[12];
    const float* bih0f = (const float*)d_in[13];
    const float* bhh0f = (const float*)d_in[14];
    const float* wih0b = (const float*)d_in[15];
    const float* whh0b = (const float*)d_in[16];
    const float* bih0b = (const float*)d_in[17];
    const float* bhh0b = (const float*)d_in[18];
    const float* wih1f = (const float*)d_in[19];
    const float* whh1f = (const float*)d_in[20];
    const float* bih1f = (const float*)d_in[21];
    const float* bhh1f = (const float*)d_in[22];
    const float* wih1b = (const float*)d_in[23];
    const float* whh1b = (const float*)d_in[24];
    const float* bih1b = (const float*)d_in[25];
    const float* bhh1b = (const float*)d_in[26];
    float* out = (float*)d_out;

    static int attr_set = 0;
    if (!attr_set) {
        cudaFuncSetAttribute(gru_layer, cudaFuncAttributeMaxDynamicSharedMemorySize, GRU_SMEM);
        cudaFuncSetAttribute(tgemm128, cudaFuncAttributeMaxDynamicSharedMemorySize, TG_SMEM);
        attr_set = 1;
    }

    void* p;
    cudaGetSymbolAddress(&p, g_qkv);   float* qkv  = (float*)p;
    cudaGetSymbolAddress(&p, g_att);   float* att  = (float*)p;
    cudaGetSymbolAddress(&p, g_x);     float* x    = (float*)p;
    cudaGetSymbolAddress(&p, g_xwT);   float* xwT  = (float*)p;
    cudaGetSymbolAddress(&p, g_hseqR); float* hsqR = (float*)p;
    cudaGetSymbolAddress(&p, g_embr);  float* embr = (float*)p;
    cudaGetSymbolAddress(&p, g_wr);    float* wr   = (float*)p;

    const size_t DIRSTRIDE = (size_t)512 * 32 * G3;

    // launches 1-3: rounds needed by QKV (plus opw)
    round_tf32_kernel<<<512, 256>>>(emb,   embr,            (MTOT * 768) / 4);
    round_tf32_kernel<<<256, 256>>>(ipw,   wr + WR_IPW,     (2304 * 768) / 4);
    round_tf32_kernel<<<128, 256>>>(opw,   wr + WR_OPW,     (768 * 768) / 4);

    // launch 4: QKV projection  <-- lands in the ncu capture window
    tgemm128<<<dim3(G3 / 128, MTOT / 128), 256, TG_SMEM>>>(embr, wr + WR_IPW, ipb, qkv, MTOT, G3, 768, 0, 0, 0);

    // remaining weight rounds
    round_tf32_kernel<<<256, 256>>>(wih0f, wr + WR_WIH0F,   (2304 * 768) / 4);
    round_tf32_kernel<<<256, 256>>>(wih0b, wr + WR_WIH0B,   (2304 * 768) / 4);
    round_tf32_kernel<<<512, 256>>>(wih1f, wr + WR_WIH1F,   (2304 * 1536) / 4);
    round_tf32_kernel<<<512, 256>>>(wih1b, wr + WR_WIH1B,   (2304 * 1536) / 4);

    // attention
    attn_scores<<<dim3(8, 8, 256), 256>>>();
    attn_softmax<<<16384, 256>>>();
    attn_av<<<dim3(8, 256), 256>>>();
    // out projection (output x rounded: feeds layer-0 GEMMs)
    tgemm128<<<dim3(768 / 128, MTOT / 128), 256, TG_SMEM>>>(att, wr + WR_OPW, opb, x, MTOT, 768, 768, 0, 0, 1);

    // GRU layers
    for (int l = 0; l < 2; l++) {
        const float* xin  = l ? hsqR : x;
        int gather        = l ? 1 : 0;
        int K             = l ? 1536 : 768;
        const float* wihF = l ? (wr + WR_WIH1F) : (wr + WR_WIH0F);
        const float* wihB = l ? (wr + WR_WIH1B) : (wr + WR_WIH0B);
        const float* bihF = l ? bih1f : bih0f;
        const float* bihB = l ? bih1b : bih0b;
        const float* whhF = l ? whh1f : whh0f;
        const float* whhB = l ? whh1b : whh0b;
        const float* bhhF = l ? bhh1f : bhh0f;
        const float* bhhB = l ? bhh1b : bhh0b;

        tgemm128<<<dim3(G3 / 128, MTOT / 128), 256, TG_SMEM>>>(xin, wihF, bihF, xwT, MTOT, G3, K, gather, 1, 0);
        tgemm128<<<dim3(G3 / 128, MTOT / 128), 256, TG_SMEM>>>(xin, wihB, bihB, xwT + DIRSTRIDE, MTOT, G3, K, gather, 1, 0);
        gru_reset<<<384, 256>>>();
        gru_layer<<<GNB, 256, GRU_SMEM>>>(whhF, whhB, bhhF, bhhB, l == 0 ? 1 : 0);
    }

    // FC + CRF + Viterbi
    fc_kernel<<<MTOT / 8, 256>>>(fcw, fcb);
    crf_nll_kernel<<<32, 32>>>(lab, cstart, cend, ctr);
    finalize_loss<<<1, 1>>>(out);
    viterbi_kernel<<<32, 32>>>(cstart, cend, ctr, out);
}

// round 14
// speedup vs baseline: 1.1631x; 1.1631x over previous
#include <cuda_runtime.h>
#include <math.h>

#define MTOT 16384   // B*S
#define G3   2304    // 3*H
#define HID  768
#define NC   9
#define GNB  96      // persistent GRU blocks (48 per dir)

// ---------------- device scratch ----------------
__device__ float g_qkv[(size_t)MTOT * G3];
__device__ float g_scores[(size_t)256 * 512 * 512];
__device__ float g_att[(size_t)MTOT * 768];
__device__ float g_x[(size_t)MTOT * 768];
__device__ float g_xwT[(size_t)2 * 512 * 32 * G3];     // [dir][s][b][G3]
__device__ float g_hseqT[(size_t)512 * 2 * 32 * 768];  // [s][dir][b][u]  (full precision, for FC)
__device__ float g_hseqR[(size_t)512 * 2 * 32 * 768];  // tf32-rounded copy (layer-1 GEMM input)
__device__ float g_hping[2 * 2 * HID * 32];            // [parity][dir][u][b] (tf32-rounded, u-major)
__device__ int   g_flags[GNB];
__device__ float g_em[(size_t)MTOT * NC];
__device__ float g_nll[32];
__device__ float g_embr[(size_t)MTOT * 768];           // tf32-rounded emb
__device__ float g_wr[12976128];                       // tf32-rounded weights (see offsets)

// weight offsets in g_wr (floats)
#define WR_IPW   0                    // 2304*768
#define WR_OPW   1769472              // 768*768
#define WR_WIH0F 2359296              // 2304*768
#define WR_WIH0B 4128768              // 2304*768
#define WR_WIH1F 5898240              // 2304*1536
#define WR_WIH1B 9437184              // 2304*1536

// ---------------- tf32 helpers ----------------
__device__ __forceinline__ unsigned cvt_tf32(float v) {
    unsigned r;
    asm("cvt.rna.tf32.f32 %0, %1;" : "=r"(r) : "f"(v));
    return r;
}
__device__ __forceinline__ float round_tf32f(float v) {
    return __uint_as_float(cvt_tf32(v));
}
__device__ __forceinline__ void mma_tf32(float* c, const unsigned* a, const unsigned* b) {
    asm volatile(
        "mma.sync.aligned.m16n8k8.row.col.f32.tf32.tf32.f32 "
        "{%0,%1,%2,%3}, {%4,%5,%6,%7}, {%8,%9}, {%0,%1,%2,%3};"
        : "+f"(c[0]), "+f"(c[1]), "+f"(c[2]), "+f"(c[3])
        : "r"(a[0]), "r"(a[1]), "r"(a[2]), "r"(a[3]), "r"(b[0]), "r"(b[1]));
}

// ---------------- fast gate nonlinearities (1 MUFU each) ----------------
__device__ __forceinline__ float ftanh(float x) {
    float t;
    asm("tanh.approx.f32 %0, %1;" : "=f"(t) : "f"(x));
    return t;
}
__device__ __forceinline__ float fsig(float x) {
    float t;
    asm("tanh.approx.f32 %0, %1;" : "=f"(t) : "f"(x * 0.5f));
    return fmaf(0.5f, t, 0.5f);
}

// ---------------- cp.async helpers ----------------
__device__ __forceinline__ void cpa16(unsigned smem_addr, const void* gptr) {
    asm volatile("cp.async.cg.shared.global [%0], [%1], 16;" :: "r"(smem_addr), "l"(gptr));
}
__device__ __forceinline__ void cpa_commit() {
    asm volatile("cp.async.commit_group;");
}

// ---------------- elementwise RNA-round to tf32 ----------------
__global__ void __launch_bounds__(256) round_tf32_kernel(
    const float* __restrict__ src, float* __restrict__ dst, int n4)
{
    int i = blockIdx.x * 256 + threadIdx.x;
    int stride = gridDim.x * 256;
    for (; i < n4; i += stride) {
        float4 v = ((const float4*)src)[i];
        v.x = round_tf32f(v.x); v.y = round_tf32f(v.y);
        v.z = round_tf32f(v.z); v.w = round_tf32f(v.w);
        ((float4*)dst)[i] = v;
    }
}

// ---------------- tf32 tensor-core NT GEMM (cp.async pipeline; inputs pre-rounded) ----------------
// C[M,N] = A[M,K] @ B[N,K]^T + bias ; M%128==0, N%128==0, K%32==0
#define TG_BUF 4608               // 128*36 words per buffer
#define TG_SMEM (4 * TG_BUF * 4)  // A[2] + B[2] buffers, bytes

__global__ void __launch_bounds__(256) tgemm128(
    const float* __restrict__ A, const float* __restrict__ B,
    const float* __restrict__ bias, float* __restrict__ C,
    int M, int N, int K, int gatherA, int permC, int roundC)
{
    extern __shared__ unsigned smu[];
    unsigned* As = smu;               // [2][128][36]
    unsigned* Bs = smu + 2 * TG_BUF;  // [2][128][36]

    const int t = threadIdx.x;
    const int lane = t & 31;
    const int wid = t >> 5;
    const int wm = wid & 3;
    const int wn = wid >> 2;
    const int g  = lane >> 2;
    const int tg = lane & 3;

    const int row0 = blockIdx.y * 128;
    const int col0 = blockIdx.x * 128;

    const int grow = t >> 1;
    const int gk   = (t & 1) * 16;
    const int rowA = row0 + grow;

    size_t gb0 = 0, gb1 = 0;
    if (gatherA) {
        int bb = rowA >> 9, sq = rowA & 511;
        gb0 = ((size_t)(sq * 2) * 32 + bb) * 768;
        gb1 = ((size_t)(sq * 2 + 1) * 32 + bb) * 768;
    }
    const float* ArowP = A + (size_t)rowA * K;
    const float* BrowP = B + (size_t)(col0 + grow) * K;

    const unsigned sbA = (unsigned)__cvta_generic_to_shared(As) + (unsigned)((grow * 36 + gk) * 4);
    const unsigned sbB = (unsigned)__cvta_generic_to_shared(Bs) + (unsigned)((grow * 36 + gk) * 4);

    float acc[2][8][4];
#pragma unroll
    for (int mt = 0; mt < 2; mt++)
#pragma unroll
        for (int nt = 0; nt < 8; nt++)
#pragma unroll
            for (int q = 0; q < 4; q++) acc[mt][nt][q] = 0.f;

    const int nch = K >> 5;

    auto issue = [&](int kt, int buf) {
        const int o = (kt << 5) + gk;
        const float* ap;
        if (gatherA) ap = A + (o < 768 ? gb0 + o : gb1 + (o - 768));
        else         ap = ArowP + o;
        const float* bp = BrowP + o;
        const unsigned da = sbA + (unsigned)(buf * TG_BUF * 4);
        const unsigned db = sbB + (unsigned)(buf * TG_BUF * 4);
#pragma unroll
        for (int j = 0; j < 4; j++) {
            cpa16(da + j * 16, ap + j * 4);
            cpa16(db + j * 16, bp + j * 4);
        }
        cpa_commit();
    };

    issue(0, 0);
    int cur = 0;

    for (int kt = 0; kt < nch; kt++) {
        const bool more = (kt + 1) < nch;
        if (more) issue(kt + 1, cur ^ 1);
        if (more) asm volatile("cp.async.wait_group 1;");
        else      asm volatile("cp.async.wait_group 0;");
        __syncthreads();

        const unsigned* Ab = As + cur * TG_BUF;
        const unsigned* Bb = Bs + cur * TG_BUF;
#pragma unroll
        for (int ks = 0; ks < 4; ks++) {
            const int kk = ks * 8;
            unsigned af[2][4];
#pragma unroll
            for (int mt = 0; mt < 2; mt++) {
                const int r = wm * 32 + mt * 16 + g;
                af[mt][0] = Ab[(r)     * 36 + kk + tg];
                af[mt][1] = Ab[(r + 8) * 36 + kk + tg];
                af[mt][2] = Ab[(r)     * 36 + kk + tg + 4];
                af[mt][3] = Ab[(r + 8) * 36 + kk + tg + 4];
            }
            unsigned bf[8][2];
#pragma unroll
            for (int nt = 0; nt < 8; nt++) {
                const int n = wn * 64 + nt * 8 + g;
                bf[nt][0] = Bb[n * 36 + kk + tg];
                bf[nt][1] = Bb[n * 36 + kk + tg + 4];
            }
#pragma unroll
            for (int mt = 0; mt < 2; mt++)
#pragma unroll
                for (int nt = 0; nt < 8; nt++)
                    mma_tf32(acc[mt][nt], af[mt], bf[nt]);
        }
        __syncthreads();
        cur ^= 1;
    }

#pragma unroll
    for (int mt = 0; mt < 2; mt++) {
        const int r = row0 + wm * 32 + mt * 16 + g;
        int cr0 = r, cr1 = r + 8;
        if (permC) {
            cr0 = (r & 511) * 32 + (r >> 9);
            cr1 = ((r + 8) & 511) * 32 + ((r + 8) >> 9);
        }
#pragma unroll
        for (int nt = 0; nt < 8; nt++) {
            const int c = col0 + wn * 64 + nt * 8 + 2 * tg;
            const float b0 = bias[c], b1 = bias[c + 1];
            float2 v0 = make_float2(acc[mt][nt][0] + b0, acc[mt][nt][1] + b1);
            float2 v1 = make_float2(acc[mt][nt][2] + b0, acc[mt][nt][3] + b1);
            if (roundC) {
                v0.x = round_tf32f(v0.x); v0.y = round_tf32f(v0.y);
                v1.x = round_tf32f(v1.x); v1.y = round_tf32f(v1.y);
            }
            *(float2*)&C[(size_t)cr0 * N + c] = v0;
            *(float2*)&C[(size_t)cr1 * N + c] = v1;
        }
    }
}

// ---------------- attention scores = scale * Q K^T ----------------
__global__ void __launch_bounds__(256) attn_scores(void)
{
    __shared__ float Qs[16][64];
    __shared__ float Ks[16][64];
    const int bh = blockIdx.z, b = bh >> 3, h = bh & 7;
    const int row0 = blockIdx.y * 64, col0 = blockIdx.x * 64;
    const int t = threadIdx.x;
    const int lr = t & 63, lk = (t >> 6) << 2;
    const int tx = t & 15, ty = t >> 4;

    const float* Qp = g_qkv + ((size_t)b * 512 + row0 + lr) * G3 + h * 96 + lk;
    const float* Kp = g_qkv + ((size_t)b * 512 + col0 + lr) * G3 + 768 + h * 96 + lk;

    float acc[4][4];
#pragma unroll
    for (int i = 0; i < 4; i++)
#pragma unroll
        for (int j = 0; j < 4; j++) acc[i][j] = 0.f;

    for (int k0 = 0; k0 < 96; k0 += 16) {
        float4 qv = *(const float4*)(Qp + k0);
        float4 kv = *(const float4*)(Kp + k0);
        __syncthreads();
        Qs[lk + 0][lr] = qv.x; Qs[lk + 1][lr] = qv.y; Qs[lk + 2][lr] = qv.z; Qs[lk + 3][lr] = qv.w;
        Ks[lk + 0][lr] = kv.x; Ks[lk + 1][lr] = kv.y; Ks[lk + 2][lr] = kv.z; Ks[lk + 3][lr] = kv.w;
        __syncthreads();
#pragma unroll
        for (int kk = 0; kk < 16; kk++) {
            float a[4], c[4];
            *(float4*)a = *(const float4*)&Qs[kk][ty << 2];
            *(float4*)c = *(const float4*)&Ks[kk][tx << 2];
#pragma unroll
            for (int i = 0; i < 4; i++)
#pragma unroll
                for (int j = 0; j < 4; j++)
                    acc[i][j] = fmaf(a[i], c[j], acc[i][j]);
        }
    }
    const float scale = 0.1020620726159657f; // 1/sqrt(96)
    float* Cb = g_scores + (size_t)bh * 262144;
#pragma unroll
    for (int i = 0; i < 4; i++)
#pragma unroll
        for (int j = 0; j < 4; j++)
            Cb[(size_t)(row0 + (ty << 2) + i) * 512 + col0 + (tx << 2) + j] = acc[i][j] * scale;
}

// ---------------- softmax over rows of 512 (warp per row) ----------------
__global__ void __launch_bounds__(256) attn_softmax(void)
{
    const int warp = threadIdx.x >> 5, lane = threadIdx.x & 31;
    const size_t row = (size_t)blockIdx.x * 8 + warp;
    float* p = g_scores + row * 512;
    float v[16];
    float m = -1e30f;
#pragma unroll
    for (int i = 0; i < 16; i++) { v[i] = p[lane + (i << 5)]; m = fmaxf(m, v[i]); }
#pragma unroll
    for (int o = 16; o; o >>= 1) m = fmaxf(m, __shfl_xor_sync(0xffffffffu, m, o));
    float s = 0.f;
#pragma unroll
    for (int i = 0; i < 16; i++) { v[i] = expf(v[i] - m); s += v[i]; }
#pragma unroll
    for (int o = 16; o; o >>= 1) s += __shfl_xor_sync(0xffffffffu, s, o);
    const float inv = 1.f / s;
#pragma unroll
    for (int i = 0; i < 16; i++) p[lane + (i << 5)] = v[i] * inv;
}

// ---------------- O = P V  (stores att RNA-rounded) ----------------
__global__ void __launch_bounds__(256) attn_av(void)
{
    __shared__ float Ps[32][64];
    __shared__ float Vs[32][96];
    const int bh = blockIdx.y, b = bh >> 3, h = bh & 7;
    const int row0 = blockIdx.x * 64;
    const int t = threadIdx.x;
    const int tx = t & 15, ty = t >> 4;
    const int lr = t & 63, lk = (t >> 6) << 3;
    const int kr = t >> 3, cq = (t & 7) * 12;

    const float* Pp = g_scores + (size_t)bh * 262144 + (size_t)(row0 + lr) * 512 + lk;
    const float* Vp = g_qkv + ((size_t)b * 512 + kr) * G3 + 1536 + h * 96 + cq;

    float acc[4][6];
#pragma unroll
    for (int i = 0; i < 4; i++)
#pragma unroll
        for (int j = 0; j < 6; j++) acc[i][j] = 0.f;

    for (int k0 = 0; k0 < 512; k0 += 32) {
        float4 p0 = *(const float4*)(Pp + k0);
        float4 p1 = *(const float4*)(Pp + k0 + 4);
        const float* vp = Vp + (size_t)k0 * G3;
        float4 v0 = *(const float4*)(vp);
        float4 v1 = *(const float4*)(vp + 4);
        float4 v2 = *(const float4*)(vp + 8);
        __syncthreads();
        Ps[lk + 0][lr] = p0.x; Ps[lk + 1][lr] = p0.y; Ps[lk + 2][lr] = p0.z; Ps[lk + 3][lr] = p0.w;
        Ps[lk + 4][lr] = p1.x; Ps[lk + 5][lr] = p1.y; Ps[lk + 6][lr] = p1.z; Ps[lk + 7][lr] = p1.w;
        *(float4*)&Vs[kr][cq + 0] = v0;
        *(float4*)&Vs[kr][cq + 4] = v1;
        *(float4*)&Vs[kr][cq + 8] = v2;
        __syncthreads();
#pragma unroll
        for (int kk = 0; kk < 32; kk++) {
            float a[4];
            *(float4*)a = *(const float4*)&Ps[kk][ty << 2];
            const float* vr = &Vs[kk][tx * 6];
#pragma unroll
            for (int i = 0; i < 4; i++)
#pragma unroll
                for (int j = 0; j < 6; j++)
                    acc[i][j] = fmaf(a[i], vr[j], acc[i][j]);
        }
    }
#pragma unroll
    for (int i = 0; i < 4; i++) {
        size_t r = (size_t)b * 512 + row0 + (ty << 2) + i;
#pragma unroll
        for (int j = 0; j < 6; j++)
            g_att[r * 768 + h * 96 + tx * 6 + j] = round_tf32f(acc[i][j]);
    }
}

// ---------------- reset flags + h ping-pong ----------------
__global__ void gru_reset(void)
{
    int i = blockIdx.x * 256 + threadIdx.x;   // grid 384 x 256 = 98304
    if (i < GNB) g_flags[i] = 0;
    g_hping[i] = 0.f;
}

// ---------------- persistent tensor-core GRU layer ----------------
// h ping-pong layout: [parity][dir][u][b]  (u-major -> 4 sectors per bf LDG)
#define GRU_WSU  (48 * 768)              // W words
#define GRU_REDW (8 * 48 * 40)           // reduce buffer words (stride 40)
#define GRU_SMEM ((GRU_WSU + GRU_REDW) * 4)

__global__ void __launch_bounds__(256) gru_layer(
    const float* __restrict__ whhF, const float* __restrict__ whhB,
    const float* __restrict__ bhhF, const float* __restrict__ bhhB,
    int writeR)
{
    extern __shared__ unsigned smu[];
    unsigned* ws = smu;                       // [48][768] swizzled tf32
    float* red = (float*)(smu + GRU_WSU);     // [8][48*40]
    __shared__ float bsh[48];

    const int tid = threadIdx.x;
    const int warp = tid >> 5, lane = tid & 31;
    const int g = lane >> 2, tg = lane & 3;
    const int blk = blockIdx.x;
    const int dir = blk / 48, ub = blk % 48;
    const int u0 = ub * 16;
    const float* W   = dir ? whhB : whhF;
    const float* bhh = dir ? bhhB : bhhF;

    for (int r = warp; r < 48; r += 8) {
        const int gr = (r >> 4) * 768 + u0 + (r & 15);
        const unsigned sw = (unsigned)((r & 7) << 2);
        unsigned* dst = ws + r * 768;
        for (int k = lane; k < 768; k += 32)
            dst[k ^ sw] = cvt_tf32(W[(size_t)gr * 768 + k]);
    }
    if (tid < 48) bsh[tid] = bhh[(tid >> 4) * 768 + u0 + (tid & 15)];
    __syncthreads();

    const int kw0 = warp * 96;
    const int ul = tid & 15;
    const int b0 = tid >> 4;
    const int b1 = b0 + 16;

    for (int s = 0; s < 512; s++) {
        const int sx = dir ? (511 - s) : s;
        const float* xwrow = g_xwT + ((size_t)(dir * 512 + sx) * 32) * G3;

        const float* xp0 = xwrow + (size_t)b0 * G3 + u0 + ul;
        const float* xp1 = xwrow + (size_t)b1 * G3 + u0 + ul;
        const float xr0 = __ldcg(xp0), xz0 = __ldcg(xp0 + 768), xn0 = __ldcg(xp0 + 1536);
        const float xr1 = __ldcg(xp1), xz1 = __ldcg(xp1 + 768), xn1 = __ldcg(xp1 + 1536);

        if (s > 0) {
            if (tid < 48) {
                // PROVEN pattern (R8/R10/R12): acquire on every poll, tight spin
                const int* fp = g_flags + dir * 48 + tid;
                int v;
                for (;;) {
                    asm volatile("ld.acquire.gpu.global.b32 %0, [%1];" : "=r"(v) : "l"(fp) : "memory");
                    if (v >= s) break;
                }
            }
            __syncthreads();
        }
        const float* hsrc = g_hping + (size_t)(((s & 1) * 2 + dir)) * HID * 32;  // [u][b]

        const float hold0 = __ldcg(&hsrc[(size_t)(u0 + ul) * 32 + b0]);
        const float hold1 = __ldcg(&hsrc[(size_t)(u0 + ul) * 32 + b1]);

        float acc[3][4][4];
#pragma unroll
        for (int mt = 0; mt < 3; mt++)
#pragma unroll
            for (int nt = 0; nt < 4; nt++)
#pragma unroll
                for (int q = 0; q < 4; q++) acc[mt][nt][q] = 0.f;

        // bf loads: addr = k*32 + batch ; lane (g,tg): k = kw0+kt*8+tg(+4), batch = nt*8+g
        // kt-outer loop: af loaded once per kt (shared by all 4 n-tiles), bf(kt+1) prefetched.
        unsigned bfc[4][2];
#pragma unroll
        for (int nt = 0; nt < 4; nt++) {
            const float* hb = hsrc + (size_t)(kw0 + tg) * 32 + nt * 8 + g;
            bfc[nt][0] = __float_as_uint(__ldcg(hb));
            bfc[nt][1] = __float_as_uint(__ldcg(hb + 4 * 32));
        }
#pragma unroll
        for (int kt = 0; kt < 12; kt++) {
            unsigned bfn[4][2] = {{0u,0u},{0u,0u},{0u,0u},{0u,0u}};
            if (kt < 11) {
#pragma unroll
                for (int nt = 0; nt < 4; nt++) {
                    const float* hb = hsrc + (size_t)(kw0 + (kt + 1) * 8 + tg) * 32 + nt * 8 + g;
                    bfn[nt][0] = __float_as_uint(__ldcg(hb));
                    bfn[nt][1] = __float_as_uint(__ldcg(hb + 4 * 32));
                }
            }
            const int kk = kw0 + kt * 8;
            unsigned af[3][4];
#pragma unroll
            for (int mt = 0; mt < 3; mt++) {
                const int r = mt * 16 + g;
                const unsigned sw = (unsigned)((r & 7) << 2);
                const unsigned* wr  = ws + r * 768;
                const unsigned* wr8 = ws + (r + 8) * 768;
                af[mt][0] = wr [(kk + tg)     ^ sw];
                af[mt][1] = wr8[(kk + tg)     ^ sw];
                af[mt][2] = wr [(kk + tg + 4) ^ sw];
                af[mt][3] = wr8[(kk + tg + 4) ^ sw];
            }
#pragma unroll
            for (int mt = 0; mt < 3; mt++)
#pragma unroll
                for (int nt = 0; nt < 4; nt++)
                    mma_tf32(acc[mt][nt], af[mt], bfc[nt]);
#pragma unroll
            for (int nt = 0; nt < 4; nt++) {
                bfc[nt][0] = bfn[nt][0];
                bfc[nt][1] = bfn[nt][1];
            }
        }

        {
            float* rp = red + warp * (48 * 40);
#pragma unroll
            for (int mt = 0; mt < 3; mt++)
#pragma unroll
                for (int nt = 0; nt < 4; nt++) {
                    const int r = mt * 16 + g, c = nt * 8 + 2 * tg;
                    *(float2*)&rp[r * 40 + c]       = make_float2(acc[mt][nt][0], acc[mt][nt][1]);
                    *(float2*)&rp[(r + 8) * 40 + c] = make_float2(acc[mt][nt][2], acc[mt][nt][3]);
                }
        }
        __syncthreads();

        float* hdst = g_hping + (size_t)((((s & 1) ^ 1) * 2 + dir)) * HID * 32;  // [u][b]
        float* hq  = g_hseqT + ((size_t)(sx * 2 + dir) * 32) * 768;
        float* hqr = g_hseqR + ((size_t)(sx * 2 + dir) * 32) * 768;
        {
            float hr0 = bsh[ul], hz0 = bsh[16 + ul], hn0 = bsh[32 + ul];
            float hr1 = hr0, hz1 = hz0, hn1 = hn0;
#pragma unroll
            for (int w = 0; w < 8; w++) {
                const float* q = red + w * (48 * 40);
                hr0 += q[ul * 40 + b0];        hr1 += q[ul * 40 + b1];
                hz0 += q[(16 + ul) * 40 + b0]; hz1 += q[(16 + ul) * 40 + b1];
                hn0 += q[(32 + ul) * 40 + b0]; hn1 += q[(32 + ul) * 40 + b1];
            }
            const float rr0 = fsig(xr0 + hr0);
            const float zz0 = fsig(xz0 + hz0);
            const float nn0 = ftanh(fmaf(rr0, hn0, xn0));
            const float hnew0 = fmaf(zz0, hold0 - nn0, nn0);
            const float rr1 = fsig(xr1 + hr1);
            const float zz1 = fsig(xz1 + hz1);
            const float nn1 = ftanh(fmaf(rr1, hn1, xn1));
            const float hnew1 = fmaf(zz1, hold1 - nn1, nn1);
            const float r0q = round_tf32f(hnew0);
            const float r1q = round_tf32f(hnew1);
            hq[(size_t)b0 * 768 + u0 + ul] = hnew0;
            hq[(size_t)b1 * 768 + u0 + ul] = hnew1;
            if (writeR) {
                hqr[(size_t)b0 * 768 + u0 + ul] = r0q;
                hqr[(size_t)b1 * 768 + u0 + ul] = r1q;
            }
            hdst[(size_t)(u0 + ul) * 32 + b0] = r0q;
            hdst[(size_t)(u0 + ul) * 32 + b1] = r1q;
        }
        __syncthreads();
        if (tid == 0) {
            asm volatile("st.release.gpu.global.b32 [%0], %1;"
                         :: "l"(g_flags + blk), "r"(s + 1) : "memory");
        }
    }
}

// ---------------- FC: em = h1 @ fc_w^T + fc_b ----------------
__global__ void __launch_bounds__(256) fc_kernel(
    const float* __restrict__ fcw, const float* __restrict__ fcb)
{
    const int warp = threadIdx.x >> 5, lane = threadIdx.x & 31;
    const int row = blockIdx.x * 8 + warp;
    const int b = row >> 9, sq = row & 511;
    const float* h0p = g_hseqT + ((size_t)(sq * 2 + 0) * 32 + b) * 768;
    const float* h1p = g_hseqT + ((size_t)(sq * 2 + 1) * 32 + b) * 768;
    float s[NC];
#pragma unroll
    for (int c = 0; c < NC; c++) s[c] = 0.f;
    for (int k = lane; k < 768; k += 32) {
        const float hv0 = h0p[k];
        const float hv1 = h1p[k];
#pragma unroll
        for (int c = 0; c < NC; c++) {
            s[c] = fmaf(hv0, __ldg(&fcw[c * 1536 + k]), s[c]);
            s[c] = fmaf(hv1, __ldg(&fcw[c * 1536 + 768 + k]), s[c]);
        }
    }
#pragma unroll
    for (int c = 0; c < NC; c++) {
        float v = s[c];
#pragma unroll
        for (int o = 16; o; o >>= 1) v += __shfl_xor_sync(0xffffffffu, v, o);
        if (lane == 0) g_em[(size_t)row * NC + c] = v + fcb[c];
    }
}

// ---------------- CRF NLL (one warp per batch) ----------------
__global__ void crf_nll_kernel(
    const int* __restrict__ labels, const float* __restrict__ start,
    const float* __restrict__ endw, const float* __restrict__ trans)
{
    int b = blockIdx.x;
    int j = threadIdx.x;
    __shared__ float al[2][NC];
    __shared__ float tr[NC * NC];
    for (int i = j; i < NC * NC; i += 32) tr[i] = trans[i];
    const float* e = g_em + (size_t)b * 512 * NC;
    if (j < NC) al[0][j] = start[j] + e[j];
    __syncwarp();
    for (int t = 1; t < 512; t++) {
        int cur = t & 1, prv = cur ^ 1;
        if (j < NC) {
            float m = -1e30f;
#pragma unroll
            for (int i = 0; i < NC; i++) m = fmaxf(m, al[prv][i] + tr[i * NC + j]);
            float s = 0.f;
#pragma unroll
            for (int i = 0; i < NC; i++) s += expf(al[prv][i] + tr[i * NC + j] - m);
            al[cur][j] = m + logf(s) + e[t * NC + j];
        }
        __syncwarp();
    }
    const int* lab = labels + b * 512;
    float acc = 0.f;
    for (int t = j; t < 512; t += 32) acc += e[t * NC + lab[t]];
    for (int t = j; t < 511; t += 32) acc += tr[lab[t] * NC + lab[t + 1]];
#pragma unroll
    for (int o = 16; o; o >>= 1) acc += __shfl_xor_sync(0xffffffffu, acc, o);
    if (j == 0) {
        float m = -1e30f;
#pragma unroll
        for (int jj = 0; jj < NC; jj++) m = fmaxf(m, al[1][jj] + endw[jj]);
        float s = 0.f;
#pragma unroll
        for (int jj = 0; jj < NC; jj++) s += expf(al[1][jj] + endw[jj] - m);
        float denom = m + logf(s);
        float num = acc + start[lab[0]] + endw[lab[511]];
        g_nll[b] = denom - num;
    }
}

__global__ void finalize_loss(float* out)
{
    float s = 0.f;
    for (int i = 0; i < 32; i++) s += g_nll[i];
    out[0] = s;
}

// ---------------- Viterbi (one warp per batch) ----------------
__global__ void viterbi_kernel(
    const float* __restrict__ start, const float* __restrict__ endw,
    const float* __restrict__ trans, float* __restrict__ out)
{
    int b = blockIdx.x;
    int j = threadIdx.x;
    __shared__ float al[2][NC];
    __shared__ float tr[NC * NC];
    __shared__ unsigned char bp[511][NC];
    for (int i = j; i < NC * NC; i += 32) tr[i] = trans[i];
    const float* e = g_em + (size_t)b * 512 * NC;
    if (j < NC) al[0][j] = start[j] + e[j];
    __syncwarp();
    for (int t = 1; t < 512; t++) {
        int cur = t & 1, prv = cur ^ 1;
        if (j < NC) {
            float best = -1e30f;
            int arg = 0;
#pragma unroll
            for (int i = 0; i < NC; i++) {
                float sc = al[prv][i] + tr[i * NC + j];
                if (sc > best) { best = sc; arg = i; }
            }
            al[cur][j] = best + e[t * NC + j];
            bp[t - 1][j] = (unsigned char)arg;
        }
        __syncwarp();
    }
    if (j == 0) {
        float best = -1e30f;
        int last = 0;
#pragma unroll
        for (int jj = 0; jj < NC; jj++) {
            float sc = al[1][jj] + endw[jj];
            if (sc > best) { best = sc; last = jj; }
        }
        float* po = out + 1 + (size_t)b * 512;
        po[511] = (float)last;
        int tag = last;
        for (int t = 510; t >= 0; t--) {
            tag = bp[t][tag];
            po[t] = (float)tag;
        }
    }
}

// ---------------- launch ----------------
extern "C" void kernel_launch(void* const* d_in, const int* in_sizes, int n_in,
                              void* d_out, int out_size)
{
    const float* emb   = (const float*)d_in[0];
    const float* ipw   = (const float*)d_in[1];
    const float* ipb   = (const float*)d_in[2];
    const float* opw   = (const float*)d_in[3];
    const float* opb   = (const float*)d_in[4];
    const float* fcw   = (const float*)d_in[5];
    const float* fcb   = (const float*)d_in[6];
    const float* cstart= (const float*)d_in[7];
    const float* cend  = (const float*)d_in[8];
    const float* ctr   = (const float*)d_in[9];
    const int*   lab   = (const int*)d_in[10];
    const float* wih0f = (const float*)d_in[11];
    const float* whh0f = (const float*)d_in[12];
    const float* bih0f = (const float*)d_in[13];
    const float* bhh0f = (const float*)d_in[14];
    const float* wih0b = (const float*)d_in[15];
    const float* whh0b = (const float*)d_in[16];
    const float* bih0b = (const float*)d_in[17];
    const float* bhh0b = (const float*)d_in[18];
    const float* wih1f = (const float*)d_in[19];
    const float* whh1f = (const float*)d_in[20];
    const float* bih1f = (const float*)d_in[21];
    const float* bhh1f = (const float*)d_in[22];
    const float* wih1b = (const float*)d_in[23];
    const float* whh1b = (const float*)d_in[24];
    const float* bih1b = (const float*)d_in[25];
    const float* bhh1b = (const float*)d_in[26];
    float* out = (float*)d_out;

    static int attr_set = 0;
    if (!attr_set) {
        cudaFuncSetAttribute(gru_layer, cudaFuncAttributeMaxDynamicSharedMemorySize, GRU_SMEM);
        cudaFuncSetAttribute(tgemm128, cudaFuncAttributeMaxDynamicSharedMemorySize, TG_SMEM);
        attr_set = 1;
    }

    void* p;
    cudaGetSymbolAddress(&p, g_qkv);   float* qkv  = (float*)p;
    cudaGetSymbolAddress(&p, g_att);   float* att  = (float*)p;
    cudaGetSymbolAddress(&p, g_x);     float* x    = (float*)p;
    cudaGetSymbolAddress(&p, g_xwT);   float* xwT  = (float*)p;
    cudaGetSymbolAddress(&p, g_hseqR); float* hsqR = (float*)p;
    cudaGetSymbolAddress(&p, g_embr);  float* embr = (float*)p;
    cudaGetSymbolAddress(&p, g_wr);    float* wr   = (float*)p;

    const size_t DIRSTRIDE = (size_t)512 * 32 * G3;

    // rounds needed by QKV (plus opw)
    round_tf32_kernel<<<512, 256>>>(emb,   embr,            (MTOT * 768) / 4);
    round_tf32_kernel<<<256, 256>>>(ipw,   wr + WR_IPW,     (2304 * 768) / 4);
    round_tf32_kernel<<<128, 256>>>(opw,   wr + WR_OPW,     (768 * 768) / 4);

    // QKV projection
    tgemm128<<<dim3(G3 / 128, MTOT / 128), 256, TG_SMEM>>>(embr, wr + WR_IPW, ipb, qkv, MTOT, G3, 768, 0, 0, 0);

    // remaining weight rounds
    round_tf32_kernel<<<256, 256>>>(wih0f, wr + WR_WIH0F,   (2304 * 768) / 4);
    round_tf32_kernel<<<256, 256>>>(wih0b, wr + WR_WIH0B,   (2304 * 768) / 4);
    round_tf32_kernel<<<512, 256>>>(wih1f, wr + WR_WIH1F,   (2304 * 1536) / 4);
    round_tf32_kernel<<<512, 256>>>(wih1b, wr + WR_WIH1B,   (2304 * 1536) / 4);

    // attention
    attn_scores<<<dim3(8, 8, 256), 256>>>();
    attn_softmax<<<16384, 256>>>();
    attn_av<<<dim3(8, 256), 256>>>();
    // out projection (output x rounded: feeds layer-0 GEMMs)
    tgemm128<<<dim3(768 / 128, MTOT / 128), 256, TG_SMEM>>>(att, wr + WR_OPW, opb, x, MTOT, 768, 768, 0, 0, 1);

    // GRU layers
    for (int l = 0; l < 2; l++) {
        const float* xin  = l ? hsqR : x;
        int gather        = l ? 1 : 0;
        int K             = l ? 1536 : 768;
        const float* wihF = l ? (wr + WR_WIH1F) : (wr + WR_WIH0F);
        const float* wihB = l ? (wr + WR_WIH1B) : (wr + WR_WIH0B);
        const float* bihF = l ? bih1f : bih0f;
        const float* bihB = l ? bih1b : bih0b;
        const float* whhF = l ? whh1f : whh0f;
        const float* whhB = l ? whh1b : whh0b;
        const float* bhhF = l ? bhh1f : bhh0f;
        const float* bhhB = l ? bhh1b : bhh0b;

        tgemm128<<<dim3(G3 / 128, MTOT / 128), 256, TG_SMEM>>>(xin, wihF, bihF, xwT, MTOT, G3, K, gather, 1, 0);
        tgemm128<<<dim3(G3 / 128, MTOT / 128), 256, TG_SMEM>>>(xin, wihB, bihB, xwT + DIRSTRIDE, MTOT, G3, K, gather, 1, 0);
        gru_reset<<<384, 256>>>();
        gru_layer<<<GNB, 256, GRU_SMEM>>>(whhF, whhB, bhhF, bhhB, l == 0 ? 1 : 0);
    }

    // FC + CRF + Viterbi
    fc_kernel<<<MTOT / 8, 256>>>(fcw, fcb);
    crf_nll_kernel<<<32, 32>>>(lab, cstart, cend, ctr);
    finalize_loss<<<1, 1>>>(out);
    viterbi_kernel<<<32, 32>>>(cstart, cend, ctr, out);
}

// round 15
// speedup vs baseline: 1.2711x; 1.0928x over previous
#include <cuda_runtime.h>
#include <math.h>

#define MTOT 16384   // B*S
#define G3   2304    // 3*H
#define HID  768
#define NC   9
#define GNB  96      // persistent GRU blocks (48 per dir)

// ---------------- device scratch ----------------
__device__ float g_qkv[(size_t)MTOT * G3];
__device__ float g_scores[(size_t)256 * 512 * 512];
__device__ float g_att[(size_t)MTOT * 768];
__device__ float g_x[(size_t)MTOT * 768];
__device__ float g_xwT[(size_t)2 * 512 * 32 * G3];     // [dir][s][b][G3]
__device__ float g_hseqT[(size_t)512 * 2 * 32 * 768];  // [s][dir][b][u]  (full precision, for FC)
__device__ float g_hseqR[(size_t)512 * 2 * 32 * 768];  // tf32-rounded copy (layer-1 GEMM input)
__device__ float g_hping[2 * 2 * HID * 32];            // [parity][dir][u][b] (tf32-rounded, u-major)
__device__ int   g_flags[GNB];
__device__ float g_em[(size_t)MTOT * NC];
__device__ float g_nll[32];
__device__ float g_embr[(size_t)MTOT * 768];           // tf32-rounded emb
__device__ float g_wr[12976128];                       // tf32-rounded weights (see offsets)

// weight offsets in g_wr (floats)
#define WR_IPW   0                    // 2304*768
#define WR_OPW   1769472              // 768*768
#define WR_WIH0F 2359296              // 2304*768
#define WR_WIH0B 4128768              // 2304*768
#define WR_WIH1F 5898240              // 2304*1536
#define WR_WIH1B 9437184              // 2304*1536

// ---------------- tf32 helpers ----------------
__device__ __forceinline__ unsigned cvt_tf32(float v) {
    unsigned r;
    asm("cvt.rna.tf32.f32 %0, %1;" : "=r"(r) : "f"(v));
    return r;
}
__device__ __forceinline__ float round_tf32f(float v) {
    return __uint_as_float(cvt_tf32(v));
}
__device__ __forceinline__ void mma_tf32(float* c, const unsigned* a, const unsigned* b) {
    asm volatile(
        "mma.sync.aligned.m16n8k8.row.col.f32.tf32.tf32.f32 "
        "{%0,%1,%2,%3}, {%4,%5,%6,%7}, {%8,%9}, {%0,%1,%2,%3};"
        : "+f"(c[0]), "+f"(c[1]), "+f"(c[2]), "+f"(c[3])
        : "r"(a[0]), "r"(a[1]), "r"(a[2]), "r"(a[3]), "r"(b[0]), "r"(b[1]));
}

// ---------------- fast gate nonlinearities (1 MUFU each) ----------------
__device__ __forceinline__ float ftanh(float x) {
    float t;
    asm("tanh.approx.f32 %0, %1;" : "=f"(t) : "f"(x));
    return t;
}
__device__ __forceinline__ float fsig(float x) {
    float t;
    asm("tanh.approx.f32 %0, %1;" : "=f"(t) : "f"(x * 0.5f));
    return fmaf(0.5f, t, 0.5f);
}

// ---------------- cp.async helpers ----------------
__device__ __forceinline__ void cpa16(unsigned smem_addr, const void* gptr) {
    asm volatile("cp.async.cg.shared.global [%0], [%1], 16;" :: "r"(smem_addr), "l"(gptr));
}
__device__ __forceinline__ void cpa_commit() {
    asm volatile("cp.async.commit_group;");
}

// ---------------- elementwise RNA-round to tf32 ----------------
__global__ void __launch_bounds__(256) round_tf32_kernel(
    const float* __restrict__ src, float* __restrict__ dst, int n4)
{
    int i = blockIdx.x * 256 + threadIdx.x;
    int stride = gridDim.x * 256;
    for (; i < n4; i += stride) {
        float4 v = ((const float4*)src)[i];
        v.x = round_tf32f(v.x); v.y = round_tf32f(v.y);
        v.z = round_tf32f(v.z); v.w = round_tf32f(v.w);
        ((float4*)dst)[i] = v;
    }
}

// ---------------- tf32 tensor-core NT GEMM (cp.async pipeline; inputs pre-rounded) ----------------
// C[M,N] = A[M,K] @ B[N,K]^T + bias ; M%128==0, N%128==0, K%32==0
#define TG_BUF 4608               // 128*36 words per buffer
#define TG_SMEM (4 * TG_BUF * 4)  // A[2] + B[2] buffers, bytes

__global__ void __launch_bounds__(256) tgemm128(
    const float* __restrict__ A, const float* __restrict__ B,
    const float* __restrict__ bias, float* __restrict__ C,
    int M, int N, int K, int gatherA, int permC, int roundC)
{
    extern __shared__ unsigned smu[];
    unsigned* As = smu;               // [2][128][36]
    unsigned* Bs = smu + 2 * TG_BUF;  // [2][128][36]

    const int t = threadIdx.x;
    const int lane = t & 31;
    const int wid = t >> 5;
    const int wm = wid & 3;
    const int wn = wid >> 2;
    const int g  = lane >> 2;
    const int tg = lane & 3;

    const int row0 = blockIdx.y * 128;
    const int col0 = blockIdx.x * 128;

    const int grow = t >> 1;
    const int gk   = (t & 1) * 16;
    const int rowA = row0 + grow;

    size_t gb0 = 0, gb1 = 0;
    if (gatherA) {
        int bb = rowA >> 9, sq = rowA & 511;
        gb0 = ((size_t)(sq * 2) * 32 + bb) * 768;
        gb1 = ((size_t)(sq * 2 + 1) * 32 + bb) * 768;
    }
    const float* ArowP = A + (size_t)rowA * K;
    const float* BrowP = B + (size_t)(col0 + grow) * K;

    const unsigned sbA = (unsigned)__cvta_generic_to_shared(As) + (unsigned)((grow * 36 + gk) * 4);
    const unsigned sbB = (unsigned)__cvta_generic_to_shared(Bs) + (unsigned)((grow * 36 + gk) * 4);

    float acc[2][8][4];
#pragma unroll
    for (int mt = 0; mt < 2; mt++)
#pragma unroll
        for (int nt = 0; nt < 8; nt++)
#pragma unroll
            for (int q = 0; q < 4; q++) acc[mt][nt][q] = 0.f;

    const int nch = K >> 5;

    auto issue = [&](int kt, int buf) {
        const int o = (kt << 5) + gk;
        const float* ap;
        if (gatherA) ap = A + (o < 768 ? gb0 + o : gb1 + (o - 768));
        else         ap = ArowP + o;
        const float* bp = BrowP + o;
        const unsigned da = sbA + (unsigned)(buf * TG_BUF * 4);
        const unsigned db = sbB + (unsigned)(buf * TG_BUF * 4);
#pragma unroll
        for (int j = 0; j < 4; j++) {
            cpa16(da + j * 16, ap + j * 4);
            cpa16(db + j * 16, bp + j * 4);
        }
        cpa_commit();
    };

    issue(0, 0);
    int cur = 0;

    for (int kt = 0; kt < nch; kt++) {
        const bool more = (kt + 1) < nch;
        if (more) issue(kt + 1, cur ^ 1);
        if (more) asm volatile("cp.async.wait_group 1;");
        else      asm volatile("cp.async.wait_group 0;");
        __syncthreads();

        const unsigned* Ab = As + cur * TG_BUF;
        const unsigned* Bb = Bs + cur * TG_BUF;
#pragma unroll
        for (int ks = 0; ks < 4; ks++) {
            const int kk = ks * 8;
            unsigned af[2][4];
#pragma unroll
            for (int mt = 0; mt < 2; mt++) {
                const int r = wm * 32 + mt * 16 + g;
                af[mt][0] = Ab[(r)     * 36 + kk + tg];
                af[mt][1] = Ab[(r + 8) * 36 + kk + tg];
                af[mt][2] = Ab[(r)     * 36 + kk + tg + 4];
                af[mt][3] = Ab[(r + 8) * 36 + kk + tg + 4];
            }
            unsigned bf[8][2];
#pragma unroll
            for (int nt = 0; nt < 8; nt++) {
                const int n = wn * 64 + nt * 8 + g;
                bf[nt][0] = Bb[n * 36 + kk + tg];
                bf[nt][1] = Bb[n * 36 + kk + tg + 4];
            }
#pragma unroll
            for (int mt = 0; mt < 2; mt++)
#pragma unroll
                for (int nt = 0; nt < 8; nt++)
                    mma_tf32(acc[mt][nt], af[mt], bf[nt]);
        }
        __syncthreads();
        cur ^= 1;
    }

#pragma unroll
    for (int mt = 0; mt < 2; mt++) {
        const int r = row0 + wm * 32 + mt * 16 + g;
        int cr0 = r, cr1 = r + 8;
        if (permC) {
            cr0 = (r & 511) * 32 + (r >> 9);
            cr1 = ((r + 8) & 511) * 32 + ((r + 8) >> 9);
        }
#pragma unroll
        for (int nt = 0; nt < 8; nt++) {
            const int c = col0 + wn * 64 + nt * 8 + 2 * tg;
            const float b0 = bias[c], b1 = bias[c + 1];
            float2 v0 = make_float2(acc[mt][nt][0] + b0, acc[mt][nt][1] + b1);
            float2 v1 = make_float2(acc[mt][nt][2] + b0, acc[mt][nt][3] + b1);
            if (roundC) {
                v0.x = round_tf32f(v0.x); v0.y = round_tf32f(v0.y);
                v1.x = round_tf32f(v1.x); v1.y = round_tf32f(v1.y);
            }
            *(float2*)&C[(size_t)cr0 * N + c] = v0;
            *(float2*)&C[(size_t)cr1 * N + c] = v1;
        }
    }
}

// ---------------- tensor-core attention scores: S = scale * Q K^T (batched) ----------------
// grid (4, 4, 256); Q/K rows have stride G3; K=96 (3 chunks). qkv must be tf32-exact.
__global__ void __launch_bounds__(256) attn_scores_t(void)
{
    extern __shared__ unsigned smu[];
    unsigned* As = smu;
    unsigned* Bs = smu + 2 * TG_BUF;

    const int t = threadIdx.x;
    const int lane = t & 31;
    const int wid = t >> 5;
    const int wm = wid & 3;
    const int wn = wid >> 2;
    const int g  = lane >> 2;
    const int tg = lane & 3;

    const int bh = blockIdx.z, b = bh >> 3, h = bh & 7;
    const int row0 = blockIdx.y * 128;
    const int col0 = blockIdx.x * 128;

    const int grow = t >> 1;
    const int gk   = (t & 1) * 16;

    const float* Ap = g_qkv + ((size_t)b * 512 + row0 + grow) * G3 + h * 96 + gk;
    const float* Bp = g_qkv + ((size_t)b * 512 + col0 + grow) * G3 + 768 + h * 96 + gk;

    const unsigned sbA = (unsigned)__cvta_generic_to_shared(As) + (unsigned)((grow * 36 + gk) * 4);
    const unsigned sbB = (unsigned)__cvta_generic_to_shared(Bs) + (unsigned)((grow * 36 + gk) * 4);

    float acc[2][8][4];
#pragma unroll
    for (int mt = 0; mt < 2; mt++)
#pragma unroll
        for (int nt = 0; nt < 8; nt++)
#pragma unroll
            for (int q = 0; q < 4; q++) acc[mt][nt][q] = 0.f;

    auto issue = [&](int kt, int buf) {
        const int o = kt << 5;
        const unsigned da = sbA + (unsigned)(buf * TG_BUF * 4);
        const unsigned db = sbB + (unsigned)(buf * TG_BUF * 4);
#pragma unroll
        for (int j = 0; j < 4; j++) {
            cpa16(da + j * 16, Ap + o + j * 4);
            cpa16(db + j * 16, Bp + o + j * 4);
        }
        cpa_commit();
    };

    issue(0, 0);
    int cur = 0;
#pragma unroll
    for (int kt = 0; kt < 3; kt++) {
        const bool more = kt < 2;
        if (more) issue(kt + 1, cur ^ 1);
        if (more) asm volatile("cp.async.wait_group 1;");
        else      asm volatile("cp.async.wait_group 0;");
        __syncthreads();

        const unsigned* Ab = As + cur * TG_BUF;
        const unsigned* Bb = Bs + cur * TG_BUF;
#pragma unroll
        for (int ks = 0; ks < 4; ks++) {
            const int kk = ks * 8;
            unsigned af[2][4];
#pragma unroll
            for (int mt = 0; mt < 2; mt++) {
                const int r = wm * 32 + mt * 16 + g;
                af[mt][0] = Ab[(r)     * 36 + kk + tg];
                af[mt][1] = Ab[(r + 8) * 36 + kk + tg];
                af[mt][2] = Ab[(r)     * 36 + kk + tg + 4];
                af[mt][3] = Ab[(r + 8) * 36 + kk + tg + 4];
            }
            unsigned bf[8][2];
#pragma unroll
            for (int nt = 0; nt < 8; nt++) {
                const int n = wn * 64 + nt * 8 + g;
                bf[nt][0] = Bb[n * 36 + kk + tg];
                bf[nt][1] = Bb[n * 36 + kk + tg + 4];
            }
#pragma unroll
            for (int mt = 0; mt < 2; mt++)
#pragma unroll
                for (int nt = 0; nt < 8; nt++)
                    mma_tf32(acc[mt][nt], af[mt], bf[nt]);
        }
        __syncthreads();
        cur ^= 1;
    }

    const float scale = 0.1020620726159657f; // 1/sqrt(96)
    float* Cb = g_scores + (size_t)bh * 262144;
#pragma unroll
    for (int mt = 0; mt < 2; mt++) {
        const int r = row0 + wm * 32 + mt * 16 + g;
#pragma unroll
        for (int nt = 0; nt < 8; nt++) {
            const int c = col0 + wn * 64 + nt * 8 + 2 * tg;
            *(float2*)&Cb[(size_t)r * 512 + c]       = make_float2(acc[mt][nt][0] * scale, acc[mt][nt][1] * scale);
            *(float2*)&Cb[(size_t)(r + 8) * 512 + c] = make_float2(acc[mt][nt][2] * scale, acc[mt][nt][3] * scale);
        }
    }
}

// ---------------- softmax over rows of 512 (warp per row) ----------------
__global__ void __launch_bounds__(256) attn_softmax(void)
{
    const int warp = threadIdx.x >> 5, lane = threadIdx.x & 31;
    const size_t row = (size_t)blockIdx.x * 8 + warp;
    float* p = g_scores + row * 512;
    float v[16];
    float m = -1e30f;
#pragma unroll
    for (int i = 0; i < 16; i++) { v[i] = p[lane + (i << 5)]; m = fmaxf(m, v[i]); }
#pragma unroll
    for (int o = 16; o; o >>= 1) m = fmaxf(m, __shfl_xor_sync(0xffffffffu, m, o));
    float s = 0.f;
#pragma unroll
    for (int i = 0; i < 16; i++) { v[i] = expf(v[i] - m); s += v[i]; }
#pragma unroll
    for (int o = 16; o; o >>= 1) s += __shfl_xor_sync(0xffffffffu, s, o);
    const float inv = 1.f / s;
#pragma unroll
    for (int i = 0; i < 16; i++) p[lane + (i << 5)] = v[i] * inv;
}

// ---------------- O = P V  (stores att RNA-rounded) ----------------
__global__ void __launch_bounds__(256) attn_av(void)
{
    __shared__ float Ps[32][64];
    __shared__ float Vs[32][96];
    const int bh = blockIdx.y, b = bh >> 3, h = bh & 7;
    const int row0 = blockIdx.x * 64;
    const int t = threadIdx.x;
    const int tx = t & 15, ty = t >> 4;
    const int lr = t & 63, lk = (t >> 6) << 3;
    const int kr = t >> 3, cq = (t & 7) * 12;

    const float* Pp = g_scores + (size_t)bh * 262144 + (size_t)(row0 + lr) * 512 + lk;
    const float* Vp = g_qkv + ((size_t)b * 512 + kr) * G3 + 1536 + h * 96 + cq;

    float acc[4][6];
#pragma unroll
    for (int i = 0; i < 4; i++)
#pragma unroll
        for (int j = 0; j < 6; j++) acc[i][j] = 0.f;

    for (int k0 = 0; k0 < 512; k0 += 32) {
        float4 p0 = *(const float4*)(Pp + k0);
        float4 p1 = *(const float4*)(Pp + k0 + 4);
        const float* vp = Vp + (size_t)k0 * G3;
        float4 v0 = *(const float4*)(vp);
        float4 v1 = *(const float4*)(vp + 4);
        float4 v2 = *(const float4*)(vp + 8);
        __syncthreads();
        Ps[lk + 0][lr] = p0.x; Ps[lk + 1][lr] = p0.y; Ps[lk + 2][lr] = p0.z; Ps[lk + 3][lr] = p0.w;
        Ps[lk + 4][lr] = p1.x; Ps[lk + 5][lr] = p1.y; Ps[lk + 6][lr] = p1.z; Ps[lk + 7][lr] = p1.w;
        *(float4*)&Vs[kr][cq + 0] = v0;
        *(float4*)&Vs[kr][cq + 4] = v1;
        *(float4*)&Vs[kr][cq + 8] = v2;
        __syncthreads();
#pragma unroll
        for (int kk = 0; kk < 32; kk++) {
            float a[4];
            *(float4*)a = *(const float4*)&Ps[kk][ty << 2];
            const float* vr = &Vs[kk][tx * 6];
#pragma unroll
            for (int i = 0; i < 4; i++)
#pragma unroll
                for (int j = 0; j < 6; j++)
                    acc[i][j] = fmaf(a[i], vr[j], acc[i][j]);
        }
    }
#pragma unroll
    for (int i = 0; i < 4; i++) {
        size_t r = (size_t)b * 512 + row0 + (ty << 2) + i;
#pragma unroll
        for (int j = 0; j < 6; j++)
            g_att[r * 768 + h * 96 + tx * 6 + j] = round_tf32f(acc[i][j]);
    }
}

// ---------------- reset flags + h ping-pong ----------------
__global__ void gru_reset(void)
{
    int i = blockIdx.x * 256 + threadIdx.x;   // grid 384 x 256 = 98304
    if (i < GNB) g_flags[i] = 0;
    g_hping[i] = 0.f;
}

// ---------------- persistent tensor-core GRU layer ----------------
// h ping-pong layout: [parity][dir][u][b]; reduce buffer stride 34 (conflict-free gate reads)
#define GRU_WSU  (48 * 768)              // W words
#define GRU_RST  34                      // reduce row stride
#define GRU_REDW (8 * 48 * GRU_RST)      // reduce buffer words
#define GRU_SMEM ((GRU_WSU + GRU_REDW) * 4)

__global__ void __launch_bounds__(256) gru_layer(
    const float* __restrict__ whhF, const float* __restrict__ whhB,
    const float* __restrict__ bhhF, const float* __restrict__ bhhB,
    int writeR)
{
    extern __shared__ unsigned smu[];
    unsigned* ws = smu;                       // [48][768] swizzled tf32
    float* red = (float*)(smu + GRU_WSU);     // [8][48*34]
    __shared__ float bsh[48];

    const int tid = threadIdx.x;
    const int warp = tid >> 5, lane = tid & 31;
    const int g = lane >> 2, tg = lane & 3;
    const int blk = blockIdx.x;
    const int dir = blk / 48, ub = blk % 48;
    const int u0 = ub * 16;
    const float* W   = dir ? whhB : whhF;
    const float* bhh = dir ? bhhB : bhhF;

    for (int r = warp; r < 48; r += 8) {
        const int gr = (r >> 4) * 768 + u0 + (r & 15);
        const unsigned sw = (unsigned)((r & 7) << 2);
        unsigned* dst = ws + r * 768;
        for (int k = lane; k < 768; k += 32)
            dst[k ^ sw] = cvt_tf32(W[(size_t)gr * 768 + k]);
    }
    if (tid < 48) bsh[tid] = bhh[(tid >> 4) * 768 + u0 + (tid & 15)];
    __syncthreads();

    const int kw0 = warp * 96;
    const int ul = tid & 15;
    const int b0 = tid >> 4;
    const int b1 = b0 + 16;

    for (int s = 0; s < 512; s++) {
        const int sx = dir ? (511 - s) : s;
        const float* xwrow = g_xwT + ((size_t)(dir * 512 + sx) * 32) * G3;

        const float* xp0 = xwrow + (size_t)b0 * G3 + u0 + ul;
        const float* xp1 = xwrow + (size_t)b1 * G3 + u0 + ul;
        const float xr0 = __ldcg(xp0), xz0 = __ldcg(xp0 + 768), xn0 = __ldcg(xp0 + 1536);
        const float xr1 = __ldcg(xp1), xz1 = __ldcg(xp1 + 768), xn1 = __ldcg(xp1 + 1536);

        if (s > 0) {
            if (tid < 48) {
                // PROVEN pattern (R8/R10/R12/R14): acquire on every poll, tight spin
                const int* fp = g_flags + dir * 48 + tid;
                int v;
                for (;;) {
                    asm volatile("ld.acquire.gpu.global.b32 %0, [%1];" : "=r"(v) : "l"(fp) : "memory");
                    if (v >= s) break;
                }
            }
            __syncthreads();
        }
        const float* hsrc = g_hping + (size_t)(((s & 1) * 2 + dir)) * HID * 32;  // [u][b]

        const float hold0 = __ldcg(&hsrc[(size_t)(u0 + ul) * 32 + b0]);
        const float hold1 = __ldcg(&hsrc[(size_t)(u0 + ul) * 32 + b1]);

        float acc[3][4][4];
#pragma unroll
        for (int mt = 0; mt < 3; mt++)
#pragma unroll
            for (int nt = 0; nt < 4; nt++)
#pragma unroll
                for (int q = 0; q < 4; q++) acc[mt][nt][q] = 0.f;

        unsigned bfc[4][2];
#pragma unroll
        for (int nt = 0; nt < 4; nt++) {
            const float* hb = hsrc + (size_t)(kw0 + tg) * 32 + nt * 8 + g;
            bfc[nt][0] = __float_as_uint(__ldcg(hb));
            bfc[nt][1] = __float_as_uint(__ldcg(hb + 4 * 32));
        }
#pragma unroll
        for (int kt = 0; kt < 12; kt++) {
            unsigned bfn[4][2] = {{0u,0u},{0u,0u},{0u,0u},{0u,0u}};
            if (kt < 11) {
#pragma unroll
                for (int nt = 0; nt < 4; nt++) {
                    const float* hb = hsrc + (size_t)(kw0 + (kt + 1) * 8 + tg) * 32 + nt * 8 + g;
                    bfn[nt][0] = __float_as_uint(__ldcg(hb));
                    bfn[nt][1] = __float_as_uint(__ldcg(hb + 4 * 32));
                }
            }
            const int kk = kw0 + kt * 8;
            unsigned af[3][4];
#pragma unroll
            for (int mt = 0; mt < 3; mt++) {
                const int r = mt * 16 + g;
                const unsigned sw = (unsigned)((r & 7) << 2);
                const unsigned* wr  = ws + r * 768;
                const unsigned* wr8 = ws + (r + 8) * 768;
                af[mt][0] = wr [(kk + tg)     ^ sw];
                af[mt][1] = wr8[(kk + tg)     ^ sw];
                af[mt][2] = wr [(kk + tg + 4) ^ sw];
                af[mt][3] = wr8[(kk + tg + 4) ^ sw];
            }
#pragma unroll
            for (int mt = 0; mt < 3; mt++)
#pragma unroll
                for (int nt = 0; nt < 4; nt++)
                    mma_tf32(acc[mt][nt], af[mt], bfc[nt]);
#pragma unroll
            for (int nt = 0; nt < 4; nt++) {
                bfc[nt][0] = bfn[nt][0];
                bfc[nt][1] = bfn[nt][1];
            }
        }

        {
            float* rp = red + warp * (48 * GRU_RST);
#pragma unroll
            for (int mt = 0; mt < 3; mt++)
#pragma unroll
                for (int nt = 0; nt < 4; nt++) {
                    const int r = mt * 16 + g, c = nt * 8 + 2 * tg;
                    *(float2*)&rp[r * GRU_RST + c]       = make_float2(acc[mt][nt][0], acc[mt][nt][1]);
                    *(float2*)&rp[(r + 8) * GRU_RST + c] = make_float2(acc[mt][nt][2], acc[mt][nt][3]);
                }
        }
        __syncthreads();

        float* hdst = g_hping + (size_t)((((s & 1) ^ 1) * 2 + dir)) * HID * 32;  // [u][b]
        float* hq  = g_hseqT + ((size_t)(sx * 2 + dir) * 32) * 768;
        float* hqr = g_hseqR + ((size_t)(sx * 2 + dir) * 32) * 768;
        {
            float hr0 = bsh[ul], hz0 = bsh[16 + ul], hn0 = bsh[32 + ul];
            float hr1 = hr0, hz1 = hz0, hn1 = hn0;
#pragma unroll
            for (int w = 0; w < 8; w++) {
                const float* q = red + w * (48 * GRU_RST);
                hr0 += q[ul * GRU_RST + b0];        hr1 += q[ul * GRU_RST + b1];
                hz0 += q[(16 + ul) * GRU_RST + b0]; hz1 += q[(16 + ul) * GRU_RST + b1];
                hn0 += q[(32 + ul) * GRU_RST + b0]; hn1 += q[(32 + ul) * GRU_RST + b1];
            }
            const float rr0 = fsig(xr0 + hr0);
            const float zz0 = fsig(xz0 + hz0);
            const float nn0 = ftanh(fmaf(rr0, hn0, xn0));
            const float hnew0 = fmaf(zz0, hold0 - nn0, nn0);
            const float rr1 = fsig(xr1 + hr1);
            const float zz1 = fsig(xz1 + hz1);
            const float nn1 = ftanh(fmaf(rr1, hn1, xn1));
            const float hnew1 = fmaf(zz1, hold1 - nn1, nn1);
            const float r0q = round_tf32f(hnew0);
            const float r1q = round_tf32f(hnew1);
            hq[(size_t)b0 * 768 + u0 + ul] = hnew0;
            hq[(size_t)b1 * 768 + u0 + ul] = hnew1;
            if (writeR) {
                hqr[(size_t)b0 * 768 + u0 + ul] = r0q;
                hqr[(size_t)b1 * 768 + u0 + ul] = r1q;
            }
            hdst[(size_t)(u0 + ul) * 32 + b0] = r0q;
            hdst[(size_t)(u0 + ul) * 32 + b1] = r1q;
        }
        __syncthreads();
        if (tid == 0) {
            asm volatile("st.release.gpu.global.b32 [%0], %1;"
                         :: "l"(g_flags + blk), "r"(s + 1) : "memory");
        }
    }
}

// ---------------- FC: em = h1 @ fc_w^T + fc_b ----------------
__global__ void __launch_bounds__(256) fc_kernel(
    const float* __restrict__ fcw, const float* __restrict__ fcb)
{
    const int warp = threadIdx.x >> 5, lane = threadIdx.x & 31;
    const int row = blockIdx.x * 8 + warp;
    const int b = row >> 9, sq = row & 511;
    const float* h0p = g_hseqT + ((size_t)(sq * 2 + 0) * 32 + b) * 768;
    const float* h1p = g_hseqT + ((size_t)(sq * 2 + 1) * 32 + b) * 768;
    float s[NC];
#pragma unroll
    for (int c = 0; c < NC; c++) s[c] = 0.f;
    for (int k = lane; k < 768; k += 32) {
        const float hv0 = h0p[k];
        const float hv1 = h1p[k];
#pragma unroll
        for (int c = 0; c < NC; c++) {
            s[c] = fmaf(hv0, __ldg(&fcw[c * 1536 + k]), s[c]);
            s[c] = fmaf(hv1, __ldg(&fcw[c * 1536 + 768 + k]), s[c]);
        }
    }
#pragma unroll
    for (int c = 0; c < NC; c++) {
        float v = s[c];
#pragma unroll
        for (int o = 16; o; o >>= 1) v += __shfl_xor_sync(0xffffffffu, v, o);
        if (lane == 0) g_em[(size_t)row * NC + c] = v + fcb[c];
    }
}

// ---------------- CRF NLL (one warp per batch) ----------------
__global__ void crf_nll_kernel(
    const int* __restrict__ labels, const float* __restrict__ start,
    const float* __restrict__ endw, const float* __restrict__ trans)
{
    int b = blockIdx.x;
    int j = threadIdx.x;
    __shared__ float al[2][NC];
    __shared__ float tr[NC * NC];
    for (int i = j; i < NC * NC; i += 32) tr[i] = trans[i];
    const float* e = g_em + (size_t)b * 512 * NC;
    if (j < NC) al[0][j] = start[j] + e[j];
    __syncwarp();
    for (int t = 1; t < 512; t++) {
        int cur = t & 1, prv = cur ^ 1;
        if (j < NC) {
            float m = -1e30f;
#pragma unroll
            for (int i = 0; i < NC; i++) m = fmaxf(m, al[prv][i] + tr[i * NC + j]);
            float s = 0.f;
#pragma unroll
            for (int i = 0; i < NC; i++) s += expf(al[prv][i] + tr[i * NC + j] - m);
            al[cur][j] = m + logf(s) + e[t * NC + j];
        }
        __syncwarp();
    }
    const int* lab = labels + b * 512;
    float acc = 0.f;
    for (int t = j; t < 512; t += 32) acc += e[t * NC + lab[t]];
    for (int t = j; t < 511; t += 32) acc += tr[lab[t] * NC + lab[t + 1]];
#pragma unroll
    for (int o = 16; o; o >>= 1) acc += __shfl_xor_sync(0xffffffffu, acc, o);
    if (j == 0) {
        float m = -1e30f;
#pragma unroll
        for (int jj = 0; jj < NC; jj++) m = fmaxf(m, al[1][jj] + endw[jj]);
        float s = 0.f;
#pragma unroll
        for (int jj = 0; jj < NC; jj++) s += expf(al[1][jj] + endw[jj] - m);
        float denom = m + logf(s);
        float num = acc + start[lab[0]] + endw[lab[511]];
        g_nll[b] = denom - num;
    }
}

__global__ void finalize_loss(float* out)
{
    float s = 0.f;
    for (int i = 0; i < 32; i++) s += g_nll[i];
    out[0] = s;
}

// ---------------- Viterbi (one warp per batch) ----------------
__global__ void viterbi_kernel(
    const float* __restrict__ start, const float* __restrict__ endw,
    const float* __restrict__ trans, float* __restrict__ out)
{
    int b = blockIdx.x;
    int j = threadIdx.x;
    __shared__ float al[2][NC];
    __shared__ float tr[NC * NC];
    __shared__ unsigned char bp[511][NC];
    for (int i = j; i < NC * NC; i += 32) tr[i] = trans[i];
    const float* e = g_em + (size_t)b * 512 * NC;
    if (j < NC) al[0][j] = start[j] + e[j];
    __syncwarp();
    for (int t = 1; t < 512; t++) {
        int cur = t & 1, prv = cur ^ 1;
        if (j < NC) {
            float best = -1e30f;
            int arg = 0;
#pragma unroll
            for (int i = 0; i < NC; i++) {
                float sc = al[prv][i] + tr[i * NC + j];
                if (sc > best) { best = sc; arg = i; }
            }
            al[cur][j] = best + e[t * NC + j];
            bp[t - 1][j] = (unsigned char)arg;
        }
        __syncwarp();
    }
    if (j == 0) {
        float best = -1e30f;
        int last = 0;
#pragma unroll
        for (int jj = 0; jj < NC; jj++) {
            float sc = al[1][jj] + endw[jj];
            if (sc > best) { best = sc; last = jj; }
        }
        float* po = out + 1 + (size_t)b * 512;
        po[511] = (float)last;
        int tag = last;
        for (int t = 510; t >= 0; t--) {
            tag = bp[t][tag];
            po[t] = (float)tag;
        }
    }
}

// ---------------- launch ----------------
extern "C" void kernel_launch(void* const* d_in, const int* in_sizes, int n_in,
                              void* d_out, int out_size)
{
    const float* emb   = (const float*)d_in[0];
    const float* ipw   = (const float*)d_in[1];
    const float* ipb   = (const float*)d_in[2];
    const float* opw   = (const float*)d_in[3];
    const float* opb   = (const float*)d_in[4];
    const float* fcw   = (const float*)d_in[5];
    const float* fcb   = (const float*)d_in[6];
    const float* cstart= (const float*)d_in[7];
    const float* cend  = (const float*)d_in[8];
    const float* ctr   = (const float*)d_in[9];
    const int*   lab   = (const int*)d_in[10];
    const float* wih0f = (const float*)d_in[11];
    const float* whh0f = (const float*)d_in[12];
    const float* bih0f = (const float*)d_in[13];
    const float* bhh0f = (const float*)d_in[14];
    const float* wih0b = (const float*)d_in[15];
    const float* whh0b = (const float*)d_in[16];
    const float* bih0b = (const float*)d_in[17];
    const float* bhh0b = (const float*)d_in[18];
    const float* wih1f = (const float*)d_in[19];
    const float* whh1f = (const float*)d_in[20];
    const float* bih1f = (const float*)d_in[21];
    const float* bhh1f = (const float*)d_in[22];
    const float* wih1b = (const float*)d_in[23];
    const float* whh1b = (const float*)d_in[24];
    const float* bih1b = (const float*)d_in[25];
    const float* bhh1b = (const float*)d_in[26];
    float* out = (float*)d_out;

    static int attr_set = 0;
    if (!attr_set) {
        cudaFuncSetAttribute(gru_layer, cudaFuncAttributeMaxDynamicSharedMemorySize, GRU_SMEM);
        cudaFuncSetAttribute(tgemm128, cudaFuncAttributeMaxDynamicSharedMemorySize, TG_SMEM);
        cudaFuncSetAttribute(attn_scores_t, cudaFuncAttributeMaxDynamicSharedMemorySize, TG_SMEM);
        attr_set = 1;
    }

    void* p;
    cudaGetSymbolAddress(&p, g_qkv);   float* qkv  = (float*)p;
    cudaGetSymbolAddress(&p, g_att);   float* att  = (float*)p;
    cudaGetSymbolAddress(&p, g_x);     float* x    = (float*)p;
    cudaGetSymbolAddress(&p, g_xwT);   float* xwT  = (float*)p;
    cudaGetSymbolAddress(&p, g_hseqR); float* hsqR = (float*)p;
    cudaGetSymbolAddress(&p, g_embr);  float* embr = (float*)p;
    cudaGetSymbolAddress(&p, g_wr);    float* wr   = (float*)p;

    const size_t DIRSTRIDE = (size_t)512 * 32 * G3;

    // rounds needed by QKV (plus opw)
    round_tf32_kernel<<<512, 256>>>(emb,   embr,            (MTOT * 768) / 4);
    round_tf32_kernel<<<256, 256>>>(ipw,   wr + WR_IPW,     (2304 * 768) / 4);
    round_tf32_kernel<<<128, 256>>>(opw,   wr + WR_OPW,     (768 * 768) / 4);

    // QKV projection (output rounded to exact tf32: feeds tensor-core scores)
    tgemm128<<<dim3(G3 / 128, MTOT / 128), 256, TG_SMEM>>>(embr, wr + WR_IPW, ipb, qkv, MTOT, G3, 768, 0, 0, 1);

    // remaining weight rounds
    round_tf32_kernel<<<256, 256>>>(wih0f, wr + WR_WIH0F,   (2304 * 768) / 4);
    round_tf32_kernel<<<256, 256>>>(wih0b, wr + WR_WIH0B,   (2304 * 768) / 4);
    round_tf32_kernel<<<512, 256>>>(wih1f, wr + WR_WIH1F,   (2304 * 1536) / 4);
    round_tf32_kernel<<<512, 256>>>(wih1b, wr + WR_WIH1B,   (2304 * 1536) / 4);

    // attention
    attn_scores_t<<<dim3(4, 4, 256), 256, TG_SMEM>>>();
    attn_softmax<<<16384, 256>>>();
    attn_av<<<dim3(8, 256), 256>>>();
    // out projection (output x rounded: feeds layer-0 GEMMs)
    tgemm128<<<dim3(768 / 128, MTOT / 128), 256, TG_SMEM>>>(att, wr + WR_OPW, opb, x, MTOT, 768, 768, 0, 0, 1);

    // GRU layers
    for (int l = 0; l < 2; l++) {
        const float* xin  = l ? hsqR : x;
        int gather        = l ? 1 : 0;
        int K             = l ? 1536 : 768;
        const float* wihF = l ? (wr + WR_WIH1F) : (wr + WR_WIH0F);
        const float* wihB = l ? (wr + WR_WIH1B) : (wr + WR_WIH0B);
        const float* bihF = l ? bih1f : bih0f;
        const float* bihB = l ? bih1b : bih0b;
        const float* whhF = l ? whh1f : whh0f;
        const float* whhB = l ? whh1b : whh0b;
        const float* bhhF = l ? bhh1f : bhh0f;
        const float* bhhB = l ? bhh1b : bhh0b;

        tgemm128<<<dim3(G3 / 128, MTOT / 128), 256, TG_SMEM>>>(xin, wihF, bihF, xwT, MTOT, G3, K, gather, 1, 0);
        tgemm128<<<dim3(G3 / 128, MTOT / 128), 256, TG_SMEM>>>(xin, wihB, bihB, xwT + DIRSTRIDE, MTOT, G3, K, gather, 1, 0);
        gru_reset<<<384, 256>>>();
        gru_layer<<<GNB, 256, GRU_SMEM>>>(whhF, whhB, bhhF, bhhB, l == 0 ? 1 : 0);
    }

    // FC + CRF + Viterbi
    fc_kernel<<<MTOT / 8, 256>>>(fcw, fcb);
    crf_nll_kernel<<<32, 32>>>(lab, cstart, cend, ctr);
    finalize_loss<<<1, 1>>>(out);
    viterbi_kernel<<<32, 32>>>(cstart, cend, ctr, out);
}

// round 16
// speedup vs baseline: 1.2756x; 1.0035x over previous
#include <cuda_runtime.h>
#include <math.h>

#define MTOT 16384   // B*S
#define G3   2304    // 3*H
#define HID  768
#define NC   9
#define GNB  96      // persistent GRU blocks (48 per dir)

// ---------------- device scratch ----------------
__device__ float g_qkv[(size_t)MTOT * G3];
__device__ float g_scores[(size_t)256 * 512 * 512];
__device__ float g_att[(size_t)MTOT * 768];
__device__ float g_x[(size_t)MTOT * 768];
__device__ float g_xwT[(size_t)2 * 512 * 32 * G3];     // [dir][s][b][G3]
__device__ float g_hseqT[(size_t)512 * 2 * 32 * 768];  // [s][dir][b][u]  (full precision, for FC)
__device__ float g_hseqR[(size_t)512 * 2 * 32 * 768];  // tf32-rounded copy (layer-1 GEMM input)
__device__ float g_hping[2 * 2 * HID * 32];            // [parity][dir][u][b] (tf32-rounded, u-major)
__device__ int   g_flags[GNB];
__device__ float g_em[(size_t)MTOT * NC];
__device__ float g_nll[32];
__device__ float g_embr[(size_t)MTOT * 768];           // tf32-rounded emb
__device__ float g_wr[12976128];                       // tf32-rounded weights (see offsets)

// weight offsets in g_wr (floats)
#define WR_IPW   0                    // 2304*768
#define WR_OPW   1769472              // 768*768
#define WR_WIH0F 2359296              // 2304*768
#define WR_WIH0B 4128768              // 2304*768
#define WR_WIH1F 5898240              // 2304*1536
#define WR_WIH1B 9437184              // 2304*1536

// ---------------- tf32 helpers ----------------
__device__ __forceinline__ unsigned cvt_tf32(float v) {
    unsigned r;
    asm("cvt.rna.tf32.f32 %0, %1;" : "=r"(r) : "f"(v));
    return r;
}
__device__ __forceinline__ float round_tf32f(float v) {
    return __uint_as_float(cvt_tf32(v));
}
__device__ __forceinline__ void mma_tf32(float* c, const unsigned* a, const unsigned* b) {
    asm volatile(
        "mma.sync.aligned.m16n8k8.row.col.f32.tf32.tf32.f32 "
        "{%0,%1,%2,%3}, {%4,%5,%6,%7}, {%8,%9}, {%0,%1,%2,%3};"
        : "+f"(c[0]), "+f"(c[1]), "+f"(c[2]), "+f"(c[3])
        : "r"(a[0]), "r"(a[1]), "r"(a[2]), "r"(a[3]), "r"(b[0]), "r"(b[1]));
}

// ---------------- fast gate nonlinearities (1 MUFU each) ----------------
__device__ __forceinline__ float ftanh(float x) {
    float t;
    asm("tanh.approx.f32 %0, %1;" : "=f"(t) : "f"(x));
    return t;
}
__device__ __forceinline__ float fsig(float x) {
    float t;
    asm("tanh.approx.f32 %0, %1;" : "=f"(t) : "f"(x * 0.5f));
    return fmaf(0.5f, t, 0.5f);
}

// ---------------- cp.async helpers ----------------
__device__ __forceinline__ void cpa16(unsigned smem_addr, const void* gptr) {
    asm volatile("cp.async.cg.shared.global [%0], [%1], 16;" :: "r"(smem_addr), "l"(gptr));
}
__device__ __forceinline__ void cpa_commit() {
    asm volatile("cp.async.commit_group;");
}

// ---------------- elementwise RNA-round to tf32 ----------------
__global__ void __launch_bounds__(256) round_tf32_kernel(
    const float* __restrict__ src, float* __restrict__ dst, int n4)
{
    int i = blockIdx.x * 256 + threadIdx.x;
    int stride = gridDim.x * 256;
    for (; i < n4; i += stride) {
        float4 v = ((const float4*)src)[i];
        v.x = round_tf32f(v.x); v.y = round_tf32f(v.y);
        v.z = round_tf32f(v.z); v.w = round_tf32f(v.w);
        ((float4*)dst)[i] = v;
    }
}

// ---------------- tf32 tensor-core NT GEMM (3-stage cp.async, single sync/chunk) ----------------
// C[M,N] = A[M,K] @ B[N,K]^T + bias ; M%128==0, N%128==0, K%32==0
#define TG_BUF 4608               // 128*36 words per buffer
#define TG_SMEM (6 * TG_BUF * 4)  // A[3] + B[3] buffers, bytes

__global__ void __launch_bounds__(256) tgemm128(
    const float* __restrict__ A, const float* __restrict__ B,
    const float* __restrict__ bias, float* __restrict__ C,
    int M, int N, int K, int gatherA, int permC, int roundC)
{
    extern __shared__ unsigned smu[];
    unsigned* As = smu;               // [3][128][36]
    unsigned* Bs = smu + 3 * TG_BUF;  // [3][128][36]

    const int t = threadIdx.x;
    const int lane = t & 31;
    const int wid = t >> 5;
    const int wm = wid & 3;
    const int wn = wid >> 2;
    const int g  = lane >> 2;
    const int tg = lane & 3;

    const int row0 = blockIdx.y * 128;
    const int col0 = blockIdx.x * 128;

    const int grow = t >> 1;
    const int gk   = (t & 1) * 16;
    const int rowA = row0 + grow;

    size_t gb0 = 0, gb1 = 0;
    if (gatherA) {
        int bb = rowA >> 9, sq = rowA & 511;
        gb0 = ((size_t)(sq * 2) * 32 + bb) * 768;
        gb1 = ((size_t)(sq * 2 + 1) * 32 + bb) * 768;
    }
    const float* ArowP = A + (size_t)rowA * K;
    const float* BrowP = B + (size_t)(col0 + grow) * K;

    const unsigned sbA = (unsigned)__cvta_generic_to_shared(As) + (unsigned)((grow * 36 + gk) * 4);
    const unsigned sbB = (unsigned)__cvta_generic_to_shared(Bs) + (unsigned)((grow * 36 + gk) * 4);

    float acc[2][8][4];
#pragma unroll
    for (int mt = 0; mt < 2; mt++)
#pragma unroll
        for (int nt = 0; nt < 8; nt++)
#pragma unroll
            for (int q = 0; q < 4; q++) acc[mt][nt][q] = 0.f;

    const int nch = K >> 5;

    auto issue = [&](int kt, int buf) {
        const int o = (kt << 5) + gk;
        const float* ap;
        if (gatherA) ap = A + (o < 768 ? gb0 + o : gb1 + (o - 768));
        else         ap = ArowP + o;
        const float* bp = BrowP + o;
        const unsigned da = sbA + (unsigned)(buf * TG_BUF * 4);
        const unsigned db = sbB + (unsigned)(buf * TG_BUF * 4);
#pragma unroll
        for (int j = 0; j < 4; j++) {
            cpa16(da + j * 16, ap + j * 4);
            cpa16(db + j * 16, bp + j * 4);
        }
        cpa_commit();
    };

    issue(0, 0);
    if (nch > 1) issue(1, 1);
    int cur = 0;

    for (int kt = 0; kt < nch; kt++) {
        if (kt + 1 < nch) asm volatile("cp.async.wait_group 1;");
        else              asm volatile("cp.async.wait_group 0;");
        __syncthreads();   // all threads past iteration kt-1's compute; chunk kt resident
        if (kt + 2 < nch) {
            int nb = cur + 2; if (nb >= 3) nb -= 3;
            issue(kt + 2, nb);
        }

        const unsigned* Ab = As + cur * TG_BUF;
        const unsigned* Bb = Bs + cur * TG_BUF;
#pragma unroll
        for (int ks = 0; ks < 4; ks++) {
            const int kk = ks * 8;
            unsigned af[2][4];
#pragma unroll
            for (int mt = 0; mt < 2; mt++) {
                const int r = wm * 32 + mt * 16 + g;
                af[mt][0] = Ab[(r)     * 36 + kk + tg];
                af[mt][1] = Ab[(r + 8) * 36 + kk + tg];
                af[mt][2] = Ab[(r)     * 36 + kk + tg + 4];
                af[mt][3] = Ab[(r + 8) * 36 + kk + tg + 4];
            }
            unsigned bf[8][2];
#pragma unroll
            for (int nt = 0; nt < 8; nt++) {
                const int n = wn * 64 + nt * 8 + g;
                bf[nt][0] = Bb[n * 36 + kk + tg];
                bf[nt][1] = Bb[n * 36 + kk + tg + 4];
            }
#pragma unroll
            for (int mt = 0; mt < 2; mt++)
#pragma unroll
                for (int nt = 0; nt < 8; nt++)
                    mma_tf32(acc[mt][nt], af[mt], bf[nt]);
        }
        cur = (cur + 1 < 3) ? cur + 1 : 0;
    }

#pragma unroll
    for (int mt = 0; mt < 2; mt++) {
        const int r = row0 + wm * 32 + mt * 16 + g;
        int cr0 = r, cr1 = r + 8;
        if (permC) {
            cr0 = (r & 511) * 32 + (r >> 9);
            cr1 = ((r + 8) & 511) * 32 + ((r + 8) >> 9);
        }
#pragma unroll
        for (int nt = 0; nt < 8; nt++) {
            const int c = col0 + wn * 64 + nt * 8 + 2 * tg;
            const float b0 = bias[c], b1 = bias[c + 1];
            float2 v0 = make_float2(acc[mt][nt][0] + b0, acc[mt][nt][1] + b1);
            float2 v1 = make_float2(acc[mt][nt][2] + b0, acc[mt][nt][3] + b1);
            if (roundC) {
                v0.x = round_tf32f(v0.x); v0.y = round_tf32f(v0.y);
                v1.x = round_tf32f(v1.x); v1.y = round_tf32f(v1.y);
            }
            *(float2*)&C[(size_t)cr0 * N + c] = v0;
            *(float2*)&C[(size_t)cr1 * N + c] = v1;
        }
    }
}

// ---------------- tensor-core attention scores: S = scale * Q K^T (batched) ----------------
// grid (4, 4, 256); Q/K rows have stride G3; K=96 (3 chunks). qkv must be tf32-exact.
__global__ void __launch_bounds__(256) attn_scores_t(void)
{
    extern __shared__ unsigned smu[];
    unsigned* As = smu;
    unsigned* Bs = smu + 3 * TG_BUF;

    const int t = threadIdx.x;
    const int lane = t & 31;
    const int wid = t >> 5;
    const int wm = wid & 3;
    const int wn = wid >> 2;
    const int g  = lane >> 2;
    const int tg = lane & 3;

    const int bh = blockIdx.z, b = bh >> 3, h = bh & 7;
    const int row0 = blockIdx.y * 128;
    const int col0 = blockIdx.x * 128;

    const int grow = t >> 1;
    const int gk   = (t & 1) * 16;

    const float* Ap = g_qkv + ((size_t)b * 512 + row0 + grow) * G3 + h * 96 + gk;
    const float* Bp = g_qkv + ((size_t)b * 512 + col0 + grow) * G3 + 768 + h * 96 + gk;

    const unsigned sbA = (unsigned)__cvta_generic_to_shared(As) + (unsigned)((grow * 36 + gk) * 4);
    const unsigned sbB = (unsigned)__cvta_generic_to_shared(Bs) + (unsigned)((grow * 36 + gk) * 4);

    float acc[2][8][4];
#pragma unroll
    for (int mt = 0; mt < 2; mt++)
#pragma unroll
        for (int nt = 0; nt < 8; nt++)
#pragma unroll
            for (int q = 0; q < 4; q++) acc[mt][nt][q] = 0.f;

    auto issue = [&](int kt, int buf) {
        const int o = kt << 5;
        const unsigned da = sbA + (unsigned)(buf * TG_BUF * 4);
        const unsigned db = sbB + (unsigned)(buf * TG_BUF * 4);
#pragma unroll
        for (int j = 0; j < 4; j++) {
            cpa16(da + j * 16, Ap + o + j * 4);
            cpa16(db + j * 16, Bp + o + j * 4);
        }
        cpa_commit();
    };

    issue(0, 0);
    issue(1, 1);
    int cur = 0;
#pragma unroll
    for (int kt = 0; kt < 3; kt++) {
        if (kt + 1 < 3) asm volatile("cp.async.wait_group 1;");
        else            asm volatile("cp.async.wait_group 0;");
        __syncthreads();
        if (kt + 2 < 3) issue(kt + 2, 2);

        const unsigned* Ab = As + cur * TG_BUF;
        const unsigned* Bb = Bs + cur * TG_BUF;
#pragma unroll
        for (int ks = 0; ks < 4; ks++) {
            const int kk = ks * 8;
            unsigned af[2][4];
#pragma unroll
            for (int mt = 0; mt < 2; mt++) {
                const int r = wm * 32 + mt * 16 + g;
                af[mt][0] = Ab[(r)     * 36 + kk + tg];
                af[mt][1] = Ab[(r + 8) * 36 + kk + tg];
                af[mt][2] = Ab[(r)     * 36 + kk + tg + 4];
                af[mt][3] = Ab[(r + 8) * 36 + kk + tg + 4];
            }
            unsigned bf[8][2];
#pragma unroll
            for (int nt = 0; nt < 8; nt++) {
                const int n = wn * 64 + nt * 8 + g;
                bf[nt][0] = Bb[n * 36 + kk + tg];
                bf[nt][1] = Bb[n * 36 + kk + tg + 4];
            }
#pragma unroll
            for (int mt = 0; mt < 2; mt++)
#pragma unroll
                for (int nt = 0; nt < 8; nt++)
                    mma_tf32(acc[mt][nt], af[mt], bf[nt]);
        }
        cur++;
    }

    const float scale = 0.1020620726159657f; // 1/sqrt(96)
    float* Cb = g_scores + (size_t)bh * 262144;
#pragma unroll
    for (int mt = 0; mt < 2; mt++) {
        const int r = row0 + wm * 32 + mt * 16 + g;
#pragma unroll
        for (int nt = 0; nt < 8; nt++) {
            const int c = col0 + wn * 64 + nt * 8 + 2 * tg;
            *(float2*)&Cb[(size_t)r * 512 + c]       = make_float2(acc[mt][nt][0] * scale, acc[mt][nt][1] * scale);
            *(float2*)&Cb[(size_t)(r + 8) * 512 + c] = make_float2(acc[mt][nt][2] * scale, acc[mt][nt][3] * scale);
        }
    }
}

// ---------------- softmax over rows of 512 (warp per row) ----------------
__global__ void __launch_bounds__(256) attn_softmax(void)
{
    const int warp = threadIdx.x >> 5, lane = threadIdx.x & 31;
    const size_t row = (size_t)blockIdx.x * 8 + warp;
    float* p = g_scores + row * 512;
    float v[16];
    float m = -1e30f;
#pragma unroll
    for (int i = 0; i < 16; i++) { v[i] = p[lane + (i << 5)]; m = fmaxf(m, v[i]); }
#pragma unroll
    for (int o = 16; o; o >>= 1) m = fmaxf(m, __shfl_xor_sync(0xffffffffu, m, o));
    float s = 0.f;
#pragma unroll
    for (int i = 0; i < 16; i++) { v[i] = expf(v[i] - m); s += v[i]; }
#pragma unroll
    for (int o = 16; o; o >>= 1) s += __shfl_xor_sync(0xffffffffu, s, o);
    const float inv = 1.f / s;
#pragma unroll
    for (int i = 0; i < 16; i++) p[lane + (i << 5)] = v[i] * inv;
}

// ---------------- O = P V  (stores att RNA-rounded) ----------------
__global__ void __launch_bounds__(256) attn_av(void)
{
    __shared__ float Ps[32][64];
    __shared__ float Vs[32][96];
    const int bh = blockIdx.y, b = bh >> 3, h = bh & 7;
    const int row0 = blockIdx.x * 64;
    const int t = threadIdx.x;
    const int tx = t & 15, ty = t >> 4;
    const int lr = t & 63, lk = (t >> 6) << 3;
    const int kr = t >> 3, cq = (t & 7) * 12;

    const float* Pp = g_scores + (size_t)bh * 262144 + (size_t)(row0 + lr) * 512 + lk;
    const float* Vp = g_qkv + ((size_t)b * 512 + kr) * G3 + 1536 + h * 96 + cq;

    float acc[4][6];
#pragma unroll
    for (int i = 0; i < 4; i++)
#pragma unroll
        for (int j = 0; j < 6; j++) acc[i][j] = 0.f;

    for (int k0 = 0; k0 < 512; k0 += 32) {
        float4 p0 = *(const float4*)(Pp + k0);
        float4 p1 = *(const float4*)(Pp + k0 + 4);
        const float* vp = Vp + (size_t)k0 * G3;
        float4 v0 = *(const float4*)(vp);
        float4 v1 = *(const float4*)(vp + 4);
        float4 v2 = *(const float4*)(vp + 8);
        __syncthreads();
        Ps[lk + 0][lr] = p0.x; Ps[lk + 1][lr] = p0.y; Ps[lk + 2][lr] = p0.z; Ps[lk + 3][lr] = p0.w;
        Ps[lk + 4][lr] = p1.x; Ps[lk + 5][lr] = p1.y; Ps[lk + 6][lr] = p1.z; Ps[lk + 7][lr] = p1.w;
        *(float4*)&Vs[kr][cq + 0] = v0;
        *(float4*)&Vs[kr][cq + 4] = v1;
        *(float4*)&Vs[kr][cq + 8] = v2;
        __syncthreads();
#pragma unroll
        for (int kk = 0; kk < 32; kk++) {
            float a[4];
            *(float4*)a = *(const float4*)&Ps[kk][ty << 2];
            const float* vr = &Vs[kk][tx * 6];
#pragma unroll
            for (int i = 0; i < 4; i++)
#pragma unroll
                for (int j = 0; j < 6; j++)
                    acc[i][j] = fmaf(a[i], vr[j], acc[i][j]);
        }
    }
#pragma unroll
    for (int i = 0; i < 4; i++) {
        size_t r = (size_t)b * 512 + row0 + (ty << 2) + i;
#pragma unroll
        for (int j = 0; j < 6; j++)
            g_att[r * 768 + h * 96 + tx * 6 + j] = round_tf32f(acc[i][j]);
    }
}

// ---------------- reset flags + h ping-pong ----------------
__global__ void gru_reset(void)
{
    int i = blockIdx.x * 256 + threadIdx.x;   // grid 384 x 256 = 98304
    if (i < GNB) g_flags[i] = 0;
    g_hping[i] = 0.f;
}

// ---------------- persistent tensor-core GRU layer ----------------
// h ping-pong layout: [parity][dir][u][b]; reduce stride 34; bf ring depth 3
#define GRU_WSU  (48 * 768)              // W words
#define GRU_RST  34                      // reduce row stride
#define GRU_REDW (8 * 48 * GRU_RST)      // reduce buffer words
#define GRU_SMEM ((GRU_WSU + GRU_REDW) * 4)

__global__ void __launch_bounds__(256) gru_layer(
    const float* __restrict__ whhF, const float* __restrict__ whhB,
    const float* __restrict__ bhhF, const float* __restrict__ bhhB,
    int writeR)
{
    extern __shared__ unsigned smu[];
    unsigned* ws = smu;                       // [48][768] swizzled tf32
    float* red = (float*)(smu + GRU_WSU);     // [8][48*34]
    __shared__ float bsh[48];

    const int tid = threadIdx.x;
    const int warp = tid >> 5, lane = tid & 31;
    const int g = lane >> 2, tg = lane & 3;
    const int blk = blockIdx.x;
    const int dir = blk / 48, ub = blk % 48;
    const int u0 = ub * 16;
    const float* W   = dir ? whhB : whhF;
    const float* bhh = dir ? bhhB : bhhF;

    for (int r = warp; r < 48; r += 8) {
        const int gr = (r >> 4) * 768 + u0 + (r & 15);
        const unsigned sw = (unsigned)((r & 7) << 2);
        unsigned* dst = ws + r * 768;
        for (int k = lane; k < 768; k += 32)
            dst[k ^ sw] = cvt_tf32(W[(size_t)gr * 768 + k]);
    }
    if (tid < 48) bsh[tid] = bhh[(tid >> 4) * 768 + u0 + (tid & 15)];
    __syncthreads();

    const int kw0 = warp * 96;
    const int ul = tid & 15;
    const int b0 = tid >> 4;
    const int b1 = b0 + 16;

    for (int s = 0; s < 512; s++) {
        const int sx = dir ? (511 - s) : s;
        const float* xwrow = g_xwT + ((size_t)(dir * 512 + sx) * 32) * G3;

        const float* xp0 = xwrow + (size_t)b0 * G3 + u0 + ul;
        const float* xp1 = xwrow + (size_t)b1 * G3 + u0 + ul;
        const float xr0 = __ldcg(xp0), xz0 = __ldcg(xp0 + 768), xn0 = __ldcg(xp0 + 1536);
        const float xr1 = __ldcg(xp1), xz1 = __ldcg(xp1 + 768), xn1 = __ldcg(xp1 + 1536);

        if (s > 0) {
            if (tid < 48) {
                // PROVEN pattern (R8..R15): acquire on every poll, tight spin
                const int* fp = g_flags + dir * 48 + tid;
                int v;
                for (;;) {
                    asm volatile("ld.acquire.gpu.global.b32 %0, [%1];" : "=r"(v) : "l"(fp) : "memory");
                    if (v >= s) break;
                }
            }
            __syncthreads();
        }
        const float* hsrc = g_hping + (size_t)(((s & 1) * 2 + dir)) * HID * 32;  // [u][b]

        const float hold0 = __ldcg(&hsrc[(size_t)(u0 + ul) * 32 + b0]);
        const float hold1 = __ldcg(&hsrc[(size_t)(u0 + ul) * 32 + b1]);

        float acc[3][4][4];
#pragma unroll
        for (int mt = 0; mt < 3; mt++)
#pragma unroll
            for (int nt = 0; nt < 4; nt++)
#pragma unroll
                for (int q = 0; q < 4; q++) acc[mt][nt][q] = 0.f;

        // bf ring depth 3: preload kt=0..2 (24 LDGs in flight), load kt+3 after consuming kt
        unsigned bfr[3][4][2];
#pragma unroll
        for (int p = 0; p < 3; p++)
#pragma unroll
            for (int nt = 0; nt < 4; nt++) {
                const float* hb = hsrc + (size_t)(kw0 + p * 8 + tg) * 32 + nt * 8 + g;
                bfr[p][nt][0] = __float_as_uint(__ldcg(hb));
                bfr[p][nt][1] = __float_as_uint(__ldcg(hb + 4 * 32));
            }
#pragma unroll
        for (int kt = 0; kt < 12; kt++) {
            const int slot = kt % 3;
            const int kk = kw0 + kt * 8;
            unsigned af[3][4];
#pragma unroll
            for (int mt = 0; mt < 3; mt++) {
                const int r = mt * 16 + g;
                const unsigned sw = (unsigned)((r & 7) << 2);
                const unsigned* wr  = ws + r * 768;
                const unsigned* wr8 = ws + (r + 8) * 768;
                af[mt][0] = wr [(kk + tg)     ^ sw];
                af[mt][1] = wr8[(kk + tg)     ^ sw];
                af[mt][2] = wr [(kk + tg + 4) ^ sw];
                af[mt][3] = wr8[(kk + tg + 4) ^ sw];
            }
#pragma unroll
            for (int mt = 0; mt < 3; mt++)
#pragma unroll
                for (int nt = 0; nt < 4; nt++)
                    mma_tf32(acc[mt][nt], af[mt], bfr[slot][nt]);
            if (kt + 3 < 12) {
#pragma unroll
                for (int nt = 0; nt < 4; nt++) {
                    const float* hb = hsrc + (size_t)(kw0 + (kt + 3) * 8 + tg) * 32 + nt * 8 + g;
                    bfr[slot][nt][0] = __float_as_uint(__ldcg(hb));
                    bfr[slot][nt][1] = __float_as_uint(__ldcg(hb + 4 * 32));
                }
            }
        }

        {
            float* rp = red + warp * (48 * GRU_RST);
#pragma unroll
            for (int mt = 0; mt < 3; mt++)
#pragma unroll
                for (int nt = 0; nt < 4; nt++) {
                    const int r = mt * 16 + g, c = nt * 8 + 2 * tg;
                    *(float2*)&rp[r * GRU_RST + c]       = make_float2(acc[mt][nt][0], acc[mt][nt][1]);
                    *(float2*)&rp[(r + 8) * GRU_RST + c] = make_float2(acc[mt][nt][2], acc[mt][nt][3]);
                }
        }
        __syncthreads();

        float* hdst = g_hping + (size_t)((((s & 1) ^ 1) * 2 + dir)) * HID * 32;  // [u][b]
        float* hq  = g_hseqT + ((size_t)(sx * 2 + dir) * 32) * 768;
        float* hqr = g_hseqR + ((size_t)(sx * 2 + dir) * 32) * 768;
        {
            float hr0 = bsh[ul], hz0 = bsh[16 + ul], hn0 = bsh[32 + ul];
            float hr1 = hr0, hz1 = hz0, hn1 = hn0;
#pragma unroll
            for (int w = 0; w < 8; w++) {
                const float* q = red + w * (48 * GRU_RST);
                hr0 += q[ul * GRU_RST + b0];        hr1 += q[ul * GRU_RST + b1];
                hz0 += q[(16 + ul) * GRU_RST + b0]; hz1 += q[(16 + ul) * GRU_RST + b1];
                hn0 += q[(32 + ul) * GRU_RST + b0]; hn1 += q[(32 + ul) * GRU_RST + b1];
            }
            const float rr0 = fsig(xr0 + hr0);
            const float zz0 = fsig(xz0 + hz0);
            const float nn0 = ftanh(fmaf(rr0, hn0, xn0));
            const float hnew0 = fmaf(zz0, hold0 - nn0, nn0);
            const float rr1 = fsig(xr1 + hr1);
            const float zz1 = fsig(xz1 + hz1);
            const float nn1 = ftanh(fmaf(rr1, hn1, xn1));
            const float hnew1 = fmaf(zz1, hold1 - nn1, nn1);
            const float r0q = round_tf32f(hnew0);
            const float r1q = round_tf32f(hnew1);
            hq[(size_t)b0 * 768 + u0 + ul] = hnew0;
            hq[(size_t)b1 * 768 + u0 + ul] = hnew1;
            if (writeR) {
                hqr[(size_t)b0 * 768 + u0 + ul] = r0q;
                hqr[(size_t)b1 * 768 + u0 + ul] = r1q;
            }
            hdst[(size_t)(u0 + ul) * 32 + b0] = r0q;
            hdst[(size_t)(u0 + ul) * 32 + b1] = r1q;
        }
        __syncthreads();
        if (tid == 0) {
            asm volatile("st.release.gpu.global.b32 [%0], %1;"
                         :: "l"(g_flags + blk), "r"(s + 1) : "memory");
        }
    }
}

// ---------------- FC: em = h1 @ fc_w^T + fc_b ----------------
__global__ void __launch_bounds__(256) fc_kernel(
    const float* __restrict__ fcw, const float* __restrict__ fcb)
{
    const int warp = threadIdx.x >> 5, lane = threadIdx.x & 31;
    const int row = blockIdx.x * 8 + warp;
    const int b = row >> 9, sq = row & 511;
    const float* h0p = g_hseqT + ((size_t)(sq * 2 + 0) * 32 + b) * 768;
    const float* h1p = g_hseqT + ((size_t)(sq * 2 + 1) * 32 + b) * 768;
    float s[NC];
#pragma unroll
    for (int c = 0; c < NC; c++) s[c] = 0.f;
    for (int k = lane; k < 768; k += 32) {
        const float hv0 = h0p[k];
        const float hv1 = h1p[k];
#pragma unroll
        for (int c = 0; c < NC; c++) {
            s[c] = fmaf(hv0, __ldg(&fcw[c * 1536 + k]), s[c]);
            s[c] = fmaf(hv1, __ldg(&fcw[c * 1536 + 768 + k]), s[c]);
        }
    }
#pragma unroll
    for (int c = 0; c < NC; c++) {
        float v = s[c];
#pragma unroll
        for (int o = 16; o; o >>= 1) v += __shfl_xor_sync(0xffffffffu, v, o);
        if (lane == 0) g_em[(size_t)row * NC + c] = v + fcb[c];
    }
}

// ---------------- CRF NLL (one warp per batch) ----------------
__global__ void crf_nll_kernel(
    const int* __restrict__ labels, const float* __restrict__ start,
    const float* __restrict__ endw, const float* __restrict__ trans)
{
    int b = blockIdx.x;
    int j = threadIdx.x;
    __shared__ float al[2][NC];
    __shared__ float tr[NC * NC];
    for (int i = j; i < NC * NC; i += 32) tr[i] = trans[i];
    const float* e = g_em + (size_t)b * 512 * NC;
    if (j < NC) al[0][j] = start[j] + e[j];
    __syncwarp();
    for (int t = 1; t < 512; t++) {
        int cur = t & 1, prv = cur ^ 1;
        if (j < NC) {
            float m = -1e30f;
#pragma unroll
            for (int i = 0; i < NC; i++) m = fmaxf(m, al[prv][i] + tr[i * NC + j]);
            float s = 0.f;
#pragma unroll
            for (int i = 0; i < NC; i++) s += expf(al[prv][i] + tr[i * NC + j] - m);
            al[cur][j] = m + logf(s) + e[t * NC + j];
        }
        __syncwarp();
    }
    const int* lab = labels + b * 512;
    float acc = 0.f;
    for (int t = j; t < 512; t += 32) acc += e[t * NC + lab[t]];
    for (int t = j; t < 511; t += 32) acc += tr[lab[t] * NC + lab[t + 1]];
#pragma unroll
    for (int o = 16; o; o >>= 1) acc += __shfl_xor_sync(0xffffffffu, acc, o);
    if (j == 0) {
        float m = -1e30f;
#pragma unroll
        for (int jj = 0; jj < NC; jj++) m = fmaxf(m, al[1][jj] + endw[jj]);
        float s = 0.f;
#pragma unroll
        for (int jj = 0; jj < NC; jj++) s += expf(al[1][jj] + endw[jj] - m);
        float denom = m + logf(s);
        float num = acc + start[lab[0]] + endw[lab[511]];
        g_nll[b] = denom - num;
    }
}

__global__ void finalize_loss(float* out)
{
    float s = 0.f;
    for (int i = 0; i < 32; i++) s += g_nll[i];
    out[0] = s;
}

// ---------------- Viterbi (one warp per batch) ----------------
__global__ void viterbi_kernel(
    const float* __restrict__ start, const float* __restrict__ endw,
    const float* __restrict__ trans, float* __restrict__ out)
{
    int b = blockIdx.x;
    int j = threadIdx.x;
    __shared__ float al[2][NC];
    __shared__ float tr[NC * NC];
    __shared__ unsigned char bp[511][NC];
    for (int i = j; i < NC * NC; i += 32) tr[i] = trans[i];
    const float* e = g_em + (size_t)b * 512 * NC;
    if (j < NC) al[0][j] = start[j] + e[j];
    __syncwarp();
    for (int t = 1; t < 512; t++) {
        int cur = t & 1, prv = cur ^ 1;
        if (j < NC) {
            float best = -1e30f;
            int arg = 0;
#pragma unroll
            for (int i = 0; i < NC; i++) {
                float sc = al[prv][i] + tr[i * NC + j];
                if (sc > best) { best = sc; arg = i; }
            }
            al[cur][j] = best + e[t * NC + j];
            bp[t - 1][j] = (unsigned char)arg;
        }
        __syncwarp();
    }
    if (j == 0) {
        float best = -1e30f;
        int last = 0;
#pragma unroll
        for (int jj = 0; jj < NC; jj++) {
            float sc = al[1][jj] + endw[jj];
            if (sc > best) { best = sc; last = jj; }
        }
        float* po = out + 1 + (size_t)b * 512;
        po[511] = (float)last;
        int tag = last;
        for (int t = 510; t >= 0; t--) {
            tag = bp[t][tag];
            po[t] = (float)tag;
        }
    }
}

// ---------------- launch ----------------
extern "C" void kernel_launch(void* const* d_in, const int* in_sizes, int n_in,
                              void* d_out, int out_size)
{
    const float* emb   = (const float*)d_in[0];
    const float* ipw   = (const float*)d_in[1];
    const float* ipb   = (const float*)d_in[2];
    const float* opw   = (const float*)d_in[3];
    const float* opb   = (const float*)d_in[4];
    const float* fcw   = (const float*)d_in[5];
    const float* fcb   = (const float*)d_in[6];
    const float* cstart= (const float*)d_in[7];
    const float* cend  = (const float*)d_in[8];
    const float* ctr   = (const float*)d_in[9];
    const int*   lab   = (const int*)d_in[10];
    const float* wih0f = (const float*)d_in[11];
    const float* whh0f = (const float*)d_in[12];
    const float* bih0f = (const float*)d_in[13];
    const float* bhh0f = (const float*)d_in[14];
    const float* wih0b = (const float*)d_in[15];
    const float* whh0b = (const float*)d_in[16];
    const float* bih0b = (const float*)d_in[17];
    const float* bhh0b = (const float*)d_in[18];
    const float* wih1f = (const float*)d_in[19];
    const float* whh1f = (const float*)d_in[20];
    const float* bih1f = (const float*)d_in[21];
    const float* bhh1f = (const float*)d_in[22];
    const float* wih1b = (const float*)d_in[23];
    const float* whh1b = (const float*)d_in[24];
    const float* bih1b = (const float*)d_in[25];
    const float* bhh1b = (const float*)d_in[26];
    float* out = (float*)d_out;

    static int attr_set = 0;
    if (!attr_set) {
        cudaFuncSetAttribute(gru_layer, cudaFuncAttributeMaxDynamicSharedMemorySize, GRU_SMEM);
        cudaFuncSetAttribute(tgemm128, cudaFuncAttributeMaxDynamicSharedMemorySize, TG_SMEM);
        cudaFuncSetAttribute(attn_scores_t, cudaFuncAttributeMaxDynamicSharedMemorySize, TG_SMEM);
        attr_set = 1;
    }

    void* p;
    cudaGetSymbolAddress(&p, g_qkv);   float* qkv  = (float*)p;
    cudaGetSymbolAddress(&p, g_att);   float* att  = (float*)p;
    cudaGetSymbolAddress(&p, g_x);     float* x    = (float*)p;
    cudaGetSymbolAddress(&p, g_xwT);   float* xwT  = (float*)p;
    cudaGetSymbolAddress(&p, g_hseqR); float* hsqR = (float*)p;
    cudaGetSymbolAddress(&p, g_embr);  float* embr = (float*)p;
    cudaGetSymbolAddress(&p, g_wr);    float* wr   = (float*)p;

    const size_t DIRSTRIDE = (size_t)512 * 32 * G3;

    // rounds needed by QKV (plus opw)
    round_tf32_kernel<<<512, 256>>>(emb,   embr,            (MTOT * 768) / 4);
    round_tf32_kernel<<<256, 256>>>(ipw,   wr + WR_IPW,     (2304 * 768) / 4);
    round_tf32_kernel<<<128, 256>>>(opw,   wr + WR_OPW,     (768 * 768) / 4);

    // QKV projection (output rounded to exact tf32: feeds tensor-core scores)
    tgemm128<<<dim3(G3 / 128, MTOT / 128), 256, TG_SMEM>>>(embr, wr + WR_IPW, ipb, qkv, MTOT, G3, 768, 0, 0, 1);

    // remaining weight rounds
    round_tf32_kernel<<<256, 256>>>(wih0f, wr + WR_WIH0F,   (2304 * 768) / 4);
    round_tf32_kernel<<<256, 256>>>(wih0b, wr + WR_WIH0B,   (2304 * 768) / 4);
    round_tf32_kernel<<<512, 256>>>(wih1f, wr + WR_WIH1F,   (2304 * 1536) / 4);
    round_tf32_kernel<<<512, 256>>>(wih1b, wr + WR_WIH1B,   (2304 * 1536) / 4);

    // attention
    attn_scores_t<<<dim3(4, 4, 256), 256, TG_SMEM>>>();
    attn_softmax<<<16384, 256>>>();
    attn_av<<<dim3(8, 256), 256>>>();
    // out projection (output x rounded: feeds layer-0 GEMMs)
    tgemm128<<<dim3(768 / 128, MTOT / 128), 256, TG_SMEM>>>(att, wr + WR_OPW, opb, x, MTOT, 768, 768, 0, 0, 1);

    // GRU layers
    for (int l = 0; l < 2; l++) {
        const float* xin  = l ? hsqR : x;
        int gather        = l ? 1 : 0;
        int K             = l ? 1536 : 768;
        const float* wihF = l ? (wr + WR_WIH1F) : (wr + WR_WIH0F);
        const float* wihB = l ? (wr + WR_WIH1B) : (wr + WR_WIH0B);
        const float* bihF = l ? bih1f : bih0f;
        const float* bihB = l ? bih1b : bih0b;
        const float* whhF = l ? whh1f : whh0f;
        const float* whhB = l ? whh1b : whh0b;
        const float* bhhF = l ? bhh1f : bhh0f;
        const float* bhhB = l ? bhh1b : bhh0b;

        tgemm128<<<dim3(G3 / 128, MTOT / 128), 256, TG_SMEM>>>(xin, wihF, bihF, xwT, MTOT, G3, K, gather, 1, 0);
        tgemm128<<<dim3(G3 / 128, MTOT / 128), 256, TG_SMEM>>>(xin, wihB, bihB, xwT + DIRSTRIDE, MTOT, G3, K, gather, 1, 0);
        gru_reset<<<384, 256>>>();
        gru_layer<<<GNB, 256, GRU_SMEM>>>(whhF, whhB, bhhF, bhhB, l == 0 ? 1 : 0);
    }

    // FC + CRF + Viterbi
    fc_kernel<<<MTOT / 8, 256>>>(fcw, fcb);
    crf_nll_kernel<<<32, 32>>>(lab, cstart, cend, ctr);
    finalize_loss<<<1, 1>>>(out);
    viterbi_kernel<<<32, 32>>>(cstart, cend, ctr, out);
}